// round 1
// baseline (speedup 1.0000x reference)
#include <cuda_runtime.h>

// Problem constants
#define TD      768
#define NHEADS  12
#define HDIM    64
#define NBATCH  2
#define NSEQ    2048
#define NROWS   (NBATCH*NSEQ)      // 4096
#define NBH     (NBATCH*NHEADS)    // 24
#define ATT_SCALE 0.125f           // 64^-0.5
#define LN_EPS  1e-5f

// Scratch (allocation-free): ~63 MB of __device__ globals
__device__ float g_h[(size_t)NROWS * TD];
__device__ float g_q[(size_t)NBH * NSEQ * HDIM];
__device__ float g_k[(size_t)NBH * NSEQ * HDIM];
__device__ float g_v[(size_t)NBH * NSEQ * HDIM];
__device__ float g_vals[(size_t)NROWS * TD];

// ---------------------------------------------------------------------------
// LayerNorm: one block per row (768 elems, 256 threads, 3 elems/thread)
// ---------------------------------------------------------------------------
__global__ __launch_bounds__(256) void ln_kernel(const float* __restrict__ x,
                                                 const float* __restrict__ gamma,
                                                 const float* __restrict__ beta) {
    int row = blockIdx.x;
    const float* xr = x + (size_t)row * TD;
    float* hr = g_h + (size_t)row * TD;

    float v[3], sum = 0.f, sq = 0.f;
#pragma unroll
    for (int p = 0; p < 3; p++) {
        v[p] = xr[threadIdx.x + p * 256];
        sum += v[p];
        sq  += v[p] * v[p];
    }
#pragma unroll
    for (int o = 16; o; o >>= 1) {
        sum += __shfl_xor_sync(0xffffffffu, sum, o);
        sq  += __shfl_xor_sync(0xffffffffu, sq,  o);
    }
    __shared__ float ssum[8], ssq[8];
    int w = threadIdx.x >> 5, l = threadIdx.x & 31;
    if (l == 0) { ssum[w] = sum; ssq[w] = sq; }
    __syncthreads();
    if (w == 0) {
        sum = ssum[l & 7];
        sq  = ssq[l & 7];
#pragma unroll
        for (int o = 4; o; o >>= 1) {
            sum += __shfl_xor_sync(0xffffffffu, sum, o);
            sq  += __shfl_xor_sync(0xffffffffu, sq,  o);
        }
        if (l == 0) { ssum[0] = sum; ssq[0] = sq; }
    }
    __syncthreads();
    float mean = ssum[0] * (1.f / TD);
    float var  = ssq[0] * (1.f / TD) - mean * mean;
    float rstd = rsqrtf(var + LN_EPS);
#pragma unroll
    for (int p = 0; p < 3; p++) {
        int i = threadIdx.x + p * 256;
        hr[i] = (v[p] - mean) * rstd * gamma[i] + beta[i];
    }
}

// ---------------------------------------------------------------------------
// Fused QKV projection GEMM: C = h @ W{q,k,v}
// 64x64x16 tiles, 256 threads, 4x4 micro-tile per thread.
// Writes directly to [bh, n, d] layout (head constant per 64-wide tile).
// ---------------------------------------------------------------------------
__global__ __launch_bounds__(256) void qkv_kernel(const float* __restrict__ Wq,
                                                  const float* __restrict__ Wk,
                                                  const float* __restrict__ Wv) {
    const float* W = (blockIdx.z == 0) ? Wq : (blockIdx.z == 1 ? Wk : Wv);
    float* C       = (blockIdx.z == 0) ? g_q : (blockIdx.z == 1 ? g_k : g_v);

    int m0 = blockIdx.x * 64;
    int n0 = blockIdx.y * 64;

    __shared__ float As[16][64];   // [k][m]
    __shared__ float Bs[16][64];   // [k][n]

    int tid = threadIdx.x;
    int tx = tid & 15, ty = tid >> 4;

    int am = tid >> 2;            // A row within tile
    int ak = (tid & 3) << 2;      // A k within tile (float4)
    int bk = tid >> 4;            // B k within tile
    int bn = (tid & 15) << 2;     // B col (float4)

    float acc[4][4] = {};

    for (int k0 = 0; k0 < TD; k0 += 16) {
        float4 a4 = *(const float4*)(g_h + (size_t)(m0 + am) * TD + k0 + ak);
        As[ak + 0][am] = a4.x; As[ak + 1][am] = a4.y;
        As[ak + 2][am] = a4.z; As[ak + 3][am] = a4.w;
        *(float4*)&Bs[bk][bn] = *(const float4*)(W + (size_t)(k0 + bk) * TD + n0 + bn);
        __syncthreads();
#pragma unroll
        for (int kk = 0; kk < 16; kk++) {
            float4 a = *(const float4*)&As[kk][ty << 2];
            float4 b = *(const float4*)&Bs[kk][tx << 2];
            float av[4] = {a.x, a.y, a.z, a.w};
            float bv[4] = {b.x, b.y, b.z, b.w};
#pragma unroll
            for (int i = 0; i < 4; i++)
#pragma unroll
                for (int j = 0; j < 4; j++)
                    acc[i][j] += av[i] * bv[j];
        }
        __syncthreads();
    }

    int head  = n0 >> 6;               // tile spans exactly one head
    int b     = m0 / NSEQ;             // tiles never straddle batch boundary
    int nbase = (m0 - b * NSEQ) + (ty << 2);
    float* Cb = C + (size_t)(b * NHEADS + head) * NSEQ * HDIM;
#pragma unroll
    for (int i = 0; i < 4; i++) {
        float4 o = make_float4(acc[i][0], acc[i][1], acc[i][2], acc[i][3]);
        *(float4*)(Cb + (size_t)(nbase + i) * HDIM + (tx << 2)) = o;
    }
}

// ---------------------------------------------------------------------------
// Attention: flash-style, one 64-query tile per block.
// smQ/smKV(K phase) hold transposed [d][col] tiles with an XOR swizzle so
// both the transpose stores and the S-loop float4 reads are conflict-free.
// ---------------------------------------------------------------------------
__device__ __forceinline__ int tswz4(int d, int cg) {
    // float index of the float4 for logical (d, col = cg*4) in a 64x64 tile
    return (d << 6) + (((cg ^ ((d >> 2) & 15))) << 2);
}

__global__ __launch_bounds__(256) void attn_kernel() {
    int bh = blockIdx.y;
    int q0 = blockIdx.x * 64;

    const float* Qg = g_q + (size_t)bh * NSEQ * HDIM;
    const float* Kg = g_k + (size_t)bh * NSEQ * HDIM;
    const float* Vg = g_v + (size_t)bh * NSEQ * HDIM;

    __shared__ float smQ[64 * 64];    // [d][i] swizzled
    __shared__ float smKV[64 * 64];   // K: [d][j] swizzled; V: [j][d] natural
    __shared__ float smP[64 * 64];    // [i][j] natural

    int tid = threadIdx.x;
    int tx = tid & 15, ty = tid >> 4;

    // Load Q tile transposed+swizzled (conflict-free stores)
#pragma unroll
    for (int p = 0; p < 4; p++) {
        int e4 = tid + p * 256;
        int r  = e4 >> 4;          // row (i), 0..63
        int cg = e4 & 15;          // d group
        float4 t = *(const float4*)(Qg + (size_t)(q0 + r) * HDIM + (cg << 2));
        int d0 = cg << 2;
        smQ[tswz4(d0 + 0, r >> 2) + (r & 3)] = t.x;
        smQ[tswz4(d0 + 1, r >> 2) + (r & 3)] = t.y;
        smQ[tswz4(d0 + 2, r >> 2) + (r & 3)] = t.z;
        smQ[tswz4(d0 + 3, r >> 2) + (r & 3)] = t.w;
    }

    float mrow[4], lrow[4], acc[4][4];
#pragma unroll
    for (int i = 0; i < 4; i++) {
        mrow[i] = -1e30f; lrow[i] = 0.f;
#pragma unroll
        for (int j = 0; j < 4; j++) acc[i][j] = 0.f;
    }

    for (int kt = 0; kt < NSEQ; kt += 64) {
        __syncthreads();  // previous O-compute done reading smKV / smP

        // Load K tile transposed+swizzled
#pragma unroll
        for (int p = 0; p < 4; p++) {
            int e4 = tid + p * 256;
            int r  = e4 >> 4;
            int cg = e4 & 15;
            float4 t = *(const float4*)(Kg + (size_t)(kt + r) * HDIM + (cg << 2));
            int d0 = cg << 2;
            smKV[tswz4(d0 + 0, r >> 2) + (r & 3)] = t.x;
            smKV[tswz4(d0 + 1, r >> 2) + (r & 3)] = t.y;
            smKV[tswz4(d0 + 2, r >> 2) + (r & 3)] = t.z;
            smKV[tswz4(d0 + 3, r >> 2) + (r & 3)] = t.w;
        }
        __syncthreads();

        // S = Q @ K^T  (s[i][j], i = ty*4+ii, j = tx*4+jj)
        float s[4][4] = {};
#pragma unroll 4
        for (int d = 0; d < HDIM; d++) {
            float4 a = *(const float4*)&smQ[tswz4(d, ty)];
            float4 b = *(const float4*)&smKV[tswz4(d, tx)];
            float av[4] = {a.x, a.y, a.z, a.w};
            float bv[4] = {b.x, b.y, b.z, b.w};
#pragma unroll
            for (int i = 0; i < 4; i++)
#pragma unroll
                for (int j = 0; j < 4; j++)
                    s[i][j] += av[i] * bv[j];
        }
        __syncthreads();  // done reading K from smKV

        // Online softmax (row groups = 16 lanes sharing ty; xor 1/2/4/8 stays in-group)
        float pr[4][4];
#pragma unroll
        for (int i = 0; i < 4; i++) {
            float mt = fmaxf(fmaxf(s[i][0], s[i][1]), fmaxf(s[i][2], s[i][3]));
#pragma unroll
            for (int o = 8; o; o >>= 1) mt = fmaxf(mt, __shfl_xor_sync(0xffffffffu, mt, o));
            float mnew = fmaxf(mrow[i], mt);
            float corr = __expf(mrow[i] - mnew);
            float ls = 0.f;
#pragma unroll
            for (int j = 0; j < 4; j++) {
                pr[i][j] = __expf(s[i][j] - mnew);
                ls += pr[i][j];
            }
#pragma unroll
            for (int o = 8; o; o >>= 1) ls += __shfl_xor_sync(0xffffffffu, ls, o);
            lrow[i] = lrow[i] * corr + ls;
            mrow[i] = mnew;
#pragma unroll
            for (int d = 0; d < 4; d++) acc[i][d] *= corr;
        }

        // Write P [i][j] (float4 rows), load V tile [j][d] natural
#pragma unroll
        for (int i = 0; i < 4; i++)
            *(float4*)&smP[((ty << 2) + i) * 64 + (tx << 2)] =
                make_float4(pr[i][0], pr[i][1], pr[i][2], pr[i][3]);
#pragma unroll
        for (int p = 0; p < 4; p++) {
            int e4 = tid + p * 256;
            int r  = e4 >> 4;
            int cg = e4 & 15;
            *(float4*)&smKV[(r << 6) + (cg << 2)] =
                *(const float4*)(Vg + (size_t)(kt + r) * HDIM + (cg << 2));
        }
        __syncthreads();

        // O += P @ V  (acc[i][d], d = tx*4+dd)
#pragma unroll 4
        for (int j = 0; j < 64; j++) {
            float4 vv = *(const float4*)&smKV[(j << 6) + (tx << 2)];
            float vvv[4] = {vv.x, vv.y, vv.z, vv.w};
            float pj[4];
#pragma unroll
            for (int i = 0; i < 4; i++) pj[i] = smP[((ty << 2) + i) * 64 + j];
#pragma unroll
            for (int i = 0; i < 4; i++)
#pragma unroll
                for (int d = 0; d < 4; d++)
                    acc[i][d] += pj[i] * vvv[d];
        }
    }

    // Epilogue: out = (acc / l) * SCALE, into [b, n, inner] layout
    int b = bh / NHEADS, head = bh % NHEADS;
    float* ob = g_vals + ((size_t)b * NSEQ + q0 + (ty << 2)) * TD + head * HDIM + (tx << 2);
#pragma unroll
    for (int i = 0; i < 4; i++) {
        float inv = ATT_SCALE / lrow[i];
        float4 o = make_float4(acc[i][0] * inv, acc[i][1] * inv,
                               acc[i][2] * inv, acc[i][3] * inv);
        *(float4*)(ob + (size_t)i * TD) = o;
    }
}

// ---------------------------------------------------------------------------
// Output projection: out = vals @ Wo + bo + x  (residual epilogue)
// ---------------------------------------------------------------------------
__global__ __launch_bounds__(256) void out_kernel(const float* __restrict__ Wo,
                                                  const float* __restrict__ bo,
                                                  const float* __restrict__ x,
                                                  float* __restrict__ out) {
    int m0 = blockIdx.x * 64;
    int n0 = blockIdx.y * 64;

    __shared__ float As[16][64];
    __shared__ float Bs[16][64];

    int tid = threadIdx.x;
    int tx = tid & 15, ty = tid >> 4;
    int am = tid >> 2;
    int ak = (tid & 3) << 2;
    int bk = tid >> 4;
    int bn = (tid & 15) << 2;

    float acc[4][4] = {};

    for (int k0 = 0; k0 < TD; k0 += 16) {
        float4 a4 = *(const float4*)(g_vals + (size_t)(m0 + am) * TD + k0 + ak);
        As[ak + 0][am] = a4.x; As[ak + 1][am] = a4.y;
        As[ak + 2][am] = a4.z; As[ak + 3][am] = a4.w;
        *(float4*)&Bs[bk][bn] = *(const float4*)(Wo + (size_t)(k0 + bk) * TD + n0 + bn);
        __syncthreads();
#pragma unroll
        for (int kk = 0; kk < 16; kk++) {
            float4 a = *(const float4*)&As[kk][ty << 2];
            float4 b = *(const float4*)&Bs[kk][tx << 2];
            float av[4] = {a.x, a.y, a.z, a.w};
            float bv[4] = {b.x, b.y, b.z, b.w};
#pragma unroll
            for (int i = 0; i < 4; i++)
#pragma unroll
                for (int j = 0; j < 4; j++)
                    acc[i][j] += av[i] * bv[j];
        }
        __syncthreads();
    }

    float4 bias = *(const float4*)(bo + n0 + (tx << 2));
#pragma unroll
    for (int i = 0; i < 4; i++) {
        size_t off = (size_t)(m0 + (ty << 2) + i) * TD + n0 + (tx << 2);
        float4 xr = *(const float4*)(x + off);
        float4 o = make_float4(acc[i][0] + bias.x + xr.x,
                               acc[i][1] + bias.y + xr.y,
                               acc[i][2] + bias.z + xr.z,
                               acc[i][3] + bias.w + xr.w);
        *(float4*)(out + off) = o;
    }
}

// ---------------------------------------------------------------------------
extern "C" void kernel_launch(void* const* d_in, const int* in_sizes, int n_in,
                              void* d_out, int out_size) {
    (void)in_sizes; (void)n_in; (void)out_size;
    const float* x     = (const float*)d_in[0];
    const float* Wq    = (const float*)d_in[1];
    const float* Wk    = (const float*)d_in[2];
    const float* Wv    = (const float*)d_in[3];
    const float* Wo    = (const float*)d_in[4];
    const float* bo    = (const float*)d_in[5];
    const float* gamma = (const float*)d_in[6];
    const float* beta  = (const float*)d_in[7];
    float* out = (float*)d_out;

    ln_kernel<<<NROWS, 256>>>(x, gamma, beta);
    qkv_kernel<<<dim3(NROWS / 64, TD / 64, 3), 256>>>(Wq, Wk, Wv);
    attn_kernel<<<dim3(NSEQ / 64, NBH), 256>>>();
    out_kernel<<<dim3(NROWS / 64, TD / 64), 256>>>(Wo, bo, x, out);
}

// round 2
// speedup vs baseline: 1.0012x; 1.0012x over previous
#include <cuda_runtime.h>

// Problem constants
#define TD      768
#define NHEADS  12
#define HDIM    64
#define NBATCH  2
#define NSEQ    2048
#define NROWS   (NBATCH*NSEQ)      // 4096
#define NBH     (NBATCH*NHEADS)    // 24
#define ATT_SCALE 0.125f           // 64^-0.5
#define LN_EPS  1e-5f

// Scratch (allocation-free): ~63 MB of __device__ globals
__device__ float g_h[(size_t)NROWS * TD];
__device__ float g_q[(size_t)NBH * NSEQ * HDIM];
__device__ float g_k[(size_t)NBH * NSEQ * HDIM];
__device__ float g_v[(size_t)NBH * NSEQ * HDIM];
__device__ float g_vals[(size_t)NROWS * TD];

// ---------------------------------------------------------------------------
// LayerNorm: one block per row (768 elems, 256 threads, 3 elems/thread)
// ---------------------------------------------------------------------------
__global__ __launch_bounds__(256) void ln_kernel(const float* __restrict__ x,
                                                 const float* __restrict__ gamma,
                                                 const float* __restrict__ beta) {
    int row = blockIdx.x;
    const float* xr = x + (size_t)row * TD;
    float* hr = g_h + (size_t)row * TD;

    float v[3], sum = 0.f, sq = 0.f;
#pragma unroll
    for (int p = 0; p < 3; p++) {
        v[p] = xr[threadIdx.x + p * 256];
        sum += v[p];
        sq  += v[p] * v[p];
    }
#pragma unroll
    for (int o = 16; o; o >>= 1) {
        sum += __shfl_xor_sync(0xffffffffu, sum, o);
        sq  += __shfl_xor_sync(0xffffffffu, sq,  o);
    }
    __shared__ float ssum[8], ssq[8];
    int w = threadIdx.x >> 5, l = threadIdx.x & 31;
    if (l == 0) { ssum[w] = sum; ssq[w] = sq; }
    __syncthreads();
    if (w == 0) {
        sum = ssum[l & 7];
        sq  = ssq[l & 7];
#pragma unroll
        for (int o = 4; o; o >>= 1) {
            sum += __shfl_xor_sync(0xffffffffu, sum, o);
            sq  += __shfl_xor_sync(0xffffffffu, sq,  o);
        }
        if (l == 0) { ssum[0] = sum; ssq[0] = sq; }
    }
    __syncthreads();
    float mean = ssum[0] * (1.f / TD);
    float var  = ssq[0] * (1.f / TD) - mean * mean;
    float rstd = rsqrtf(var + LN_EPS);
#pragma unroll
    for (int p = 0; p < 3; p++) {
        int i = threadIdx.x + p * 256;
        hr[i] = (v[p] - mean) * rstd * gamma[i] + beta[i];
    }
}

// ---------------------------------------------------------------------------
// Fused QKV projection GEMM: C = h @ W{q,k,v}
// 64x64x16 tiles, 256 threads, 4x4 micro-tile per thread.
// Writes directly to [bh, n, d] layout (head constant per 64-wide tile).
// ---------------------------------------------------------------------------
__global__ __launch_bounds__(256) void qkv_kernel(const float* __restrict__ Wq,
                                                  const float* __restrict__ Wk,
                                                  const float* __restrict__ Wv) {
    const float* W = (blockIdx.z == 0) ? Wq : (blockIdx.z == 1 ? Wk : Wv);
    float* C       = (blockIdx.z == 0) ? g_q : (blockIdx.z == 1 ? g_k : g_v);

    int m0 = blockIdx.x * 64;
    int n0 = blockIdx.y * 64;

    __shared__ float As[16][64];   // [k][m]
    __shared__ float Bs[16][64];   // [k][n]

    int tid = threadIdx.x;
    int tx = tid & 15, ty = tid >> 4;

    int am = tid >> 2;            // A row within tile
    int ak = (tid & 3) << 2;      // A k within tile (float4)
    int bk = tid >> 4;            // B k within tile
    int bn = (tid & 15) << 2;     // B col (float4)

    float acc[4][4] = {};

    for (int k0 = 0; k0 < TD; k0 += 16) {
        float4 a4 = *(const float4*)(g_h + (size_t)(m0 + am) * TD + k0 + ak);
        As[ak + 0][am] = a4.x; As[ak + 1][am] = a4.y;
        As[ak + 2][am] = a4.z; As[ak + 3][am] = a4.w;
        *(float4*)&Bs[bk][bn] = *(const float4*)(W + (size_t)(k0 + bk) * TD + n0 + bn);
        __syncthreads();
#pragma unroll
        for (int kk = 0; kk < 16; kk++) {
            float4 a = *(const float4*)&As[kk][ty << 2];
            float4 b = *(const float4*)&Bs[kk][tx << 2];
            float av[4] = {a.x, a.y, a.z, a.w};
            float bv[4] = {b.x, b.y, b.z, b.w};
#pragma unroll
            for (int i = 0; i < 4; i++)
#pragma unroll
                for (int j = 0; j < 4; j++)
                    acc[i][j] += av[i] * bv[j];
        }
        __syncthreads();
    }

    int head  = n0 >> 6;               // tile spans exactly one head
    int b     = m0 / NSEQ;             // tiles never straddle batch boundary
    int nbase = (m0 - b * NSEQ) + (ty << 2);
    float* Cb = C + (size_t)(b * NHEADS + head) * NSEQ * HDIM;
#pragma unroll
    for (int i = 0; i < 4; i++) {
        float4 o = make_float4(acc[i][0], acc[i][1], acc[i][2], acc[i][3]);
        *(float4*)(Cb + (size_t)(nbase + i) * HDIM + (tx << 2)) = o;
    }
}

// ---------------------------------------------------------------------------
// Attention: flash-style, one 64-query tile per block.
// smQ/smKV(K phase) hold transposed [d][col] tiles with an XOR swizzle so
// both the transpose stores and the S-loop float4 reads are conflict-free.
// ---------------------------------------------------------------------------
__device__ __forceinline__ int tswz4(int d, int cg) {
    // float index of the float4 for logical (d, col = cg*4) in a 64x64 tile
    return (d << 6) + (((cg ^ ((d >> 2) & 15))) << 2);
}

__global__ __launch_bounds__(256) void attn_kernel() {
    int bh = blockIdx.y;
    int q0 = blockIdx.x * 64;

    const float* Qg = g_q + (size_t)bh * NSEQ * HDIM;
    const float* Kg = g_k + (size_t)bh * NSEQ * HDIM;
    const float* Vg = g_v + (size_t)bh * NSEQ * HDIM;

    __shared__ float smQ[64 * 64];    // [d][i] swizzled
    __shared__ float smKV[64 * 64];   // K: [d][j] swizzled; V: [j][d] natural
    __shared__ float smP[64 * 64];    // [i][j] natural

    int tid = threadIdx.x;
    int tx = tid & 15, ty = tid >> 4;

    // Load Q tile transposed+swizzled (conflict-free stores)
#pragma unroll
    for (int p = 0; p < 4; p++) {
        int e4 = tid + p * 256;
        int r  = e4 >> 4;          // row (i), 0..63
        int cg = e4 & 15;          // d group
        float4 t = *(const float4*)(Qg + (size_t)(q0 + r) * HDIM + (cg << 2));
        int d0 = cg << 2;
        smQ[tswz4(d0 + 0, r >> 2) + (r & 3)] = t.x;
        smQ[tswz4(d0 + 1, r >> 2) + (r & 3)] = t.y;
        smQ[tswz4(d0 + 2, r >> 2) + (r & 3)] = t.z;
        smQ[tswz4(d0 + 3, r >> 2) + (r & 3)] = t.w;
    }

    float mrow[4], lrow[4], acc[4][4];
#pragma unroll
    for (int i = 0; i < 4; i++) {
        mrow[i] = -1e30f; lrow[i] = 0.f;
#pragma unroll
        for (int j = 0; j < 4; j++) acc[i][j] = 0.f;
    }

    for (int kt = 0; kt < NSEQ; kt += 64) {
        __syncthreads();  // previous O-compute done reading smKV / smP

        // Load K tile transposed+swizzled
#pragma unroll
        for (int p = 0; p < 4; p++) {
            int e4 = tid + p * 256;
            int r  = e4 >> 4;
            int cg = e4 & 15;
            float4 t = *(const float4*)(Kg + (size_t)(kt + r) * HDIM + (cg << 2));
            int d0 = cg << 2;
            smKV[tswz4(d0 + 0, r >> 2) + (r & 3)] = t.x;
            smKV[tswz4(d0 + 1, r >> 2) + (r & 3)] = t.y;
            smKV[tswz4(d0 + 2, r >> 2) + (r & 3)] = t.z;
            smKV[tswz4(d0 + 3, r >> 2) + (r & 3)] = t.w;
        }
        __syncthreads();

        // S = Q @ K^T  (s[i][j], i = ty*4+ii, j = tx*4+jj)
        float s[4][4] = {};
#pragma unroll 4
        for (int d = 0; d < HDIM; d++) {
            float4 a = *(const float4*)&smQ[tswz4(d, ty)];
            float4 b = *(const float4*)&smKV[tswz4(d, tx)];
            float av[4] = {a.x, a.y, a.z, a.w};
            float bv[4] = {b.x, b.y, b.z, b.w};
#pragma unroll
            for (int i = 0; i < 4; i++)
#pragma unroll
                for (int j = 0; j < 4; j++)
                    s[i][j] += av[i] * bv[j];
        }
        __syncthreads();  // done reading K from smKV

        // Online softmax (row groups = 16 lanes sharing ty; xor 1/2/4/8 stays in-group)
        float pr[4][4];
#pragma unroll
        for (int i = 0; i < 4; i++) {
            float mt = fmaxf(fmaxf(s[i][0], s[i][1]), fmaxf(s[i][2], s[i][3]));
#pragma unroll
            for (int o = 8; o; o >>= 1) mt = fmaxf(mt, __shfl_xor_sync(0xffffffffu, mt, o));
            float mnew = fmaxf(mrow[i], mt);
            float corr = __expf(mrow[i] - mnew);
            float ls = 0.f;
#pragma unroll
            for (int j = 0; j < 4; j++) {
                pr[i][j] = __expf(s[i][j] - mnew);
                ls += pr[i][j];
            }
#pragma unroll
            for (int o = 8; o; o >>= 1) ls += __shfl_xor_sync(0xffffffffu, ls, o);
            lrow[i] = lrow[i] * corr + ls;
            mrow[i] = mnew;
#pragma unroll
            for (int d = 0; d < 4; d++) acc[i][d] *= corr;
        }

        // Write P [i][j] (float4 rows), load V tile [j][d] natural
#pragma unroll
        for (int i = 0; i < 4; i++)
            *(float4*)&smP[((ty << 2) + i) * 64 + (tx << 2)] =
                make_float4(pr[i][0], pr[i][1], pr[i][2], pr[i][3]);
#pragma unroll
        for (int p = 0; p < 4; p++) {
            int e4 = tid + p * 256;
            int r  = e4 >> 4;
            int cg = e4 & 15;
            *(float4*)&smKV[(r << 6) + (cg << 2)] =
                *(const float4*)(Vg + (size_t)(kt + r) * HDIM + (cg << 2));
        }
        __syncthreads();

        // O += P @ V  (acc[i][d], d = tx*4+dd)
#pragma unroll 4
        for (int j = 0; j < 64; j++) {
            float4 vv = *(const float4*)&smKV[(j << 6) + (tx << 2)];
            float vvv[4] = {vv.x, vv.y, vv.z, vv.w};
            float pj[4];
#pragma unroll
            for (int i = 0; i < 4; i++) pj[i] = smP[((ty << 2) + i) * 64 + j];
#pragma unroll
            for (int i = 0; i < 4; i++)
#pragma unroll
                for (int d = 0; d < 4; d++)
                    acc[i][d] += pj[i] * vvv[d];
        }
    }

    // Epilogue: out = (acc / l) * SCALE, into [b, n, inner] layout
    int b = bh / NHEADS, head = bh % NHEADS;
    float* ob = g_vals + ((size_t)b * NSEQ + q0 + (ty << 2)) * TD + head * HDIM + (tx << 2);
#pragma unroll
    for (int i = 0; i < 4; i++) {
        float inv = ATT_SCALE / lrow[i];
        float4 o = make_float4(acc[i][0] * inv, acc[i][1] * inv,
                               acc[i][2] * inv, acc[i][3] * inv);
        *(float4*)(ob + (size_t)i * TD) = o;
    }
}

// ---------------------------------------------------------------------------
// Output projection: out = vals @ Wo + bo + x  (residual epilogue)
// ---------------------------------------------------------------------------
__global__ __launch_bounds__(256) void out_kernel(const float* __restrict__ Wo,
                                                  const float* __restrict__ bo,
                                                  const float* __restrict__ x,
                                                  float* __restrict__ out) {
    int m0 = blockIdx.x * 64;
    int n0 = blockIdx.y * 64;

    __shared__ float As[16][64];
    __shared__ float Bs[16][64];

    int tid = threadIdx.x;
    int tx = tid & 15, ty = tid >> 4;
    int am = tid >> 2;
    int ak = (tid & 3) << 2;
    int bk = tid >> 4;
    int bn = (tid & 15) << 2;

    float acc[4][4] = {};

    for (int k0 = 0; k0 < TD; k0 += 16) {
        float4 a4 = *(const float4*)(g_vals + (size_t)(m0 + am) * TD + k0 + ak);
        As[ak + 0][am] = a4.x; As[ak + 1][am] = a4.y;
        As[ak + 2][am] = a4.z; As[ak + 3][am] = a4.w;
        *(float4*)&Bs[bk][bn] = *(const float4*)(Wo + (size_t)(k0 + bk) * TD + n0 + bn);
        __syncthreads();
#pragma unroll
        for (int kk = 0; kk < 16; kk++) {
            float4 a = *(const float4*)&As[kk][ty << 2];
            float4 b = *(const float4*)&Bs[kk][tx << 2];
            float av[4] = {a.x, a.y, a.z, a.w};
            float bv[4] = {b.x, b.y, b.z, b.w};
#pragma unroll
            for (int i = 0; i < 4; i++)
#pragma unroll
                for (int j = 0; j < 4; j++)
                    acc[i][j] += av[i] * bv[j];
        }
        __syncthreads();
    }

    float4 bias = *(const float4*)(bo + n0 + (tx << 2));
#pragma unroll
    for (int i = 0; i < 4; i++) {
        size_t off = (size_t)(m0 + (ty << 2) + i) * TD + n0 + (tx << 2);
        float4 xr = *(const float4*)(x + off);
        float4 o = make_float4(acc[i][0] + bias.x + xr.x,
                               acc[i][1] + bias.y + xr.y,
                               acc[i][2] + bias.z + xr.z,
                               acc[i][3] + bias.w + xr.w);
        *(float4*)(out + off) = o;
    }
}

// ---------------------------------------------------------------------------
extern "C" void kernel_launch(void* const* d_in, const int* in_sizes, int n_in,
                              void* d_out, int out_size) {
    (void)in_sizes; (void)n_in; (void)out_size;
    const float* x     = (const float*)d_in[0];
    const float* Wq    = (const float*)d_in[1];
    const float* Wk    = (const float*)d_in[2];
    const float* Wv    = (const float*)d_in[3];
    const float* Wo    = (const float*)d_in[4];
    const float* bo    = (const float*)d_in[5];
    const float* gamma = (const float*)d_in[6];
    const float* beta  = (const float*)d_in[7];
    float* out = (float*)d_out;

    ln_kernel<<<NROWS, 256>>>(x, gamma, beta);
    qkv_kernel<<<dim3(NROWS / 64, TD / 64, 3), 256>>>(Wq, Wk, Wv);
    attn_kernel<<<dim3(NSEQ / 64, NBH), 256>>>();
    out_kernel<<<dim3(NROWS / 64, TD / 64), 256>>>(Wo, bo, x, out);
}

// round 4
// speedup vs baseline: 6.9976x; 6.9889x over previous
#include <cuda_runtime.h>
#include <cuda_bf16.h>
#include <cstdint>

#define TD 768
#define NHEADS 12
#define HDIM 64
#define NSEQ 2048
#define NROWS 4096
#define NBH 24
#define ATT_SCALE 0.125f
#define LN_EPS 1e-5f

typedef __nv_bfloat16 bf16;

__device__ bf16 g_h[(size_t)NROWS * TD];
__device__ bf16 g_wt[4][(size_t)TD * TD];            // W^T [n][k]
__device__ bf16 g_q[(size_t)NBH * NSEQ * HDIM];
__device__ bf16 g_k[(size_t)NBH * NSEQ * HDIM];
__device__ bf16 g_v[(size_t)NBH * NSEQ * HDIM];
__device__ bf16 g_vt[(size_t)NBH * HDIM * NSEQ];     // V^T [bh][d][seq]
__device__ bf16 g_vals[(size_t)NROWS * TD];

// ---------------- helpers ----------------
__device__ __forceinline__ uint32_t smem_u32(const void* p) {
    uint32_t a;
    asm("{ .reg .u64 t; cvta.to.shared.u64 t, %1; cvt.u32.u64 %0, t; }" : "=r"(a) : "l"(p));
    return a;
}
__device__ __forceinline__ uint32_t row128(int r, int cb) {
    uint32_t o = (uint32_t)(r * 128 + cb);
    return o ^ ((o >> 3) & 0x70);
}
__device__ __forceinline__ uint32_t pack2(float a, float b) {
    return (uint32_t)__bfloat16_as_ushort(__float2bfloat16_rn(a)) |
           ((uint32_t)__bfloat16_as_ushort(__float2bfloat16_rn(b)) << 16);
}
__device__ __forceinline__ void ldsm4(uint32_t& r0, uint32_t& r1, uint32_t& r2, uint32_t& r3,
                                      uint32_t addr) {
    asm volatile("ldmatrix.sync.aligned.m8n8.x4.shared.b16 {%0,%1,%2,%3}, [%4];"
        : "=r"(r0), "=r"(r1), "=r"(r2), "=r"(r3) : "r"(addr));
}
__device__ __forceinline__ void mma16816(float* c, const uint32_t* a, const uint32_t* b) {
    asm volatile("mma.sync.aligned.m16n8k16.row.col.f32.bf16.bf16.f32 "
        "{%0,%1,%2,%3}, {%4,%5,%6,%7}, {%8,%9}, {%0,%1,%2,%3};"
        : "+f"(c[0]), "+f"(c[1]), "+f"(c[2]), "+f"(c[3])
        : "r"(a[0]), "r"(a[1]), "r"(a[2]), "r"(a[3]), "r"(b[0]), "r"(b[1]));
}

// ---------------- LayerNorm -> bf16 ----------------
__global__ __launch_bounds__(256) void ln_kernel(const float* __restrict__ x,
                                                 const float* __restrict__ gamma,
                                                 const float* __restrict__ beta) {
    int row = blockIdx.x;
    const float* xr = x + (size_t)row * TD;
    float v[3], sum = 0.f, sq = 0.f;
#pragma unroll
    for (int p = 0; p < 3; p++) {
        v[p] = xr[threadIdx.x + p * 256];
        sum += v[p]; sq += v[p] * v[p];
    }
#pragma unroll
    for (int o = 16; o; o >>= 1) {
        sum += __shfl_xor_sync(~0u, sum, o);
        sq  += __shfl_xor_sync(~0u, sq, o);
    }
    __shared__ float ss[8], sv[8];
    int w = threadIdx.x >> 5, l = threadIdx.x & 31;
    if (l == 0) { ss[w] = sum; sv[w] = sq; }
    __syncthreads();
    if (w == 0) {
        sum = ss[l & 7]; sq = sv[l & 7];
#pragma unroll
        for (int o = 4; o; o >>= 1) {
            sum += __shfl_xor_sync(~0u, sum, o);
            sq  += __shfl_xor_sync(~0u, sq, o);
        }
        if (l == 0) { ss[0] = sum; sv[0] = sq; }
    }
    __syncthreads();
    float mean = ss[0] * (1.f / TD);
    float rstd = rsqrtf(sv[0] * (1.f / TD) - mean * mean + LN_EPS);
#pragma unroll
    for (int p = 0; p < 3; p++) {
        int i = threadIdx.x + p * 256;
        g_h[(size_t)row * TD + i] =
            __float2bfloat16_rn((v[p] - mean) * rstd * gamma[i] + beta[i]);
    }
}

// ---------------- Weight transpose: wt[n][k] = W[k][n] (bf16) ----------------
__global__ __launch_bounds__(256) void wtrans_kernel(const float* __restrict__ Wq,
                                                     const float* __restrict__ Wk,
                                                     const float* __restrict__ Wv,
                                                     const float* __restrict__ Wo) {
    int z = blockIdx.z;
    const float* W = (z == 0) ? Wq : (z == 1) ? Wk : (z == 2) ? Wv : Wo;
    __shared__ float t[32][33];
    int n0 = blockIdx.x * 32, k0 = blockIdx.y * 32;
    int tx = threadIdx.x, ty = threadIdx.y;
#pragma unroll
    for (int i = 0; i < 4; i++)
        t[ty + 8 * i][tx] = W[(size_t)(k0 + ty + 8 * i) * TD + n0 + tx];
    __syncthreads();
#pragma unroll
    for (int i = 0; i < 4; i++)
        g_wt[z][(size_t)(n0 + ty + 8 * i) * TD + k0 + tx] =
            __float2bfloat16_rn(t[tx][ty + 8 * i]);
}

// ---------------- core 128x128 GEMM mainloop (mma.sync) ----------------
// A: [4096][768] bf16 row-major; Bt: [768][768] bf16 [n][k]. 256 threads, 8 warps 2x4.
__device__ __forceinline__ void gemm128(const bf16* __restrict__ A, const bf16* __restrict__ Bt,
                                        char* smem, float c[4][4][4], int m0, int n0) {
    int tid = threadIdx.x, warp = tid >> 5, lane = tid & 31;
    int wm = (warp >> 2) * 64, wn = (warp & 3) * 32;
    uint32_t sb = smem_u32(smem);
    int arow = wm + (lane & 15);
    int acolx = (lane & 16) ? 16 : 0;
    int brow0 = wn + ((lane & 16) ? 8 : 0) + (lane & 7);
    int bcolx = (lane & 8) ? 16 : 0;

    for (int i = 0; i < 12; i++) {
#pragma unroll
        for (int p = 0; p < 4; p++) {
            int idx = tid + p * 256;
            int r = idx >> 3, ch = idx & 7;
            uint32_t sw = row128(r, ch * 16);
            *(uint4*)(smem + sw)         = *(const uint4*)(A  + (size_t)(m0 + r) * TD + i * 64 + ch * 8);
            *(uint4*)(smem + 16384 + sw) = *(const uint4*)(Bt + (size_t)(n0 + r) * TD + i * 64 + ch * 8);
        }
        __syncthreads();
#pragma unroll
        for (int ks = 0; ks < 4; ks++) {
            uint32_t af[4][4], bfr[4][2];
#pragma unroll
            for (int mf = 0; mf < 4; mf++)
                ldsm4(af[mf][0], af[mf][1], af[mf][2], af[mf][3],
                      sb + row128(arow + mf * 16, ks * 32 + acolx));
#pragma unroll
            for (int j = 0; j < 4; j += 2)
                ldsm4(bfr[j][0], bfr[j][1], bfr[j + 1][0], bfr[j + 1][1],
                      sb + 16384 + row128(brow0 + j * 8, ks * 32 + bcolx));
#pragma unroll
            for (int mf = 0; mf < 4; mf++)
#pragma unroll
                for (int nf = 0; nf < 4; nf++)
                    mma16816(c[mf][nf], af[mf], bfr[nf]);
        }
        __syncthreads();
    }
}

// ---------------- QKV GEMM ----------------
__global__ __launch_bounds__(256) void qkv_kernel() {
    __shared__ char smem[32768];
    int z = blockIdx.z;
    int m0 = blockIdx.x * 128, n0 = blockIdx.y * 128;
    float c[4][4][4] = {};
    gemm128(g_h, g_wt[z], smem, c, m0, n0);

    bf16* G = (z == 0) ? g_q : (z == 1) ? g_k : g_v;
    int tid = threadIdx.x, warp = tid >> 5, lane = tid & 31;
    int wm = (warp >> 2) * 64, wn = (warp & 3) * 32;
#pragma unroll
    for (int mf = 0; mf < 4; mf++) {
        int row = m0 + wm + mf * 16 + (lane >> 2);
        int batch = row >> 11, seq = row & (NSEQ - 1);
#pragma unroll
        for (int nf = 0; nf < 4; nf++) {
            int col = n0 + wn + nf * 8 + 2 * (lane & 3);
            int head = col >> 6, d = col & 63;
            bf16* D = G + ((size_t)(batch * NHEADS + head) * NSEQ + seq) * HDIM + d;
            *(uint32_t*)D = pack2(c[mf][nf][0], c[mf][nf][1]);
            *(uint32_t*)(D + 8 * HDIM) = pack2(c[mf][nf][2], c[mf][nf][3]);
        }
    }
}

// ---------------- V transpose: g_vt[bh][d][s] = g_v[bh][s][d] ----------------
__global__ __launch_bounds__(256) void vtrans_kernel() {
    int bh = blockIdx.y, s0 = blockIdx.x * 64;
    __shared__ bf16 t[64][72];
    const bf16* src = g_v + ((size_t)bh * NSEQ + s0) * HDIM;
    int tid = threadIdx.x;
#pragma unroll
    for (int p = 0; p < 2; p++) {
        int o = tid + p * 256;
        int r = o >> 3, s = o & 7;
        *(uint4*)&t[r][s * 8] = *(const uint4*)(src + (size_t)r * HDIM + s * 8);
    }
    __syncthreads();
    bf16* dst = g_vt + (size_t)bh * HDIM * NSEQ + s0;
#pragma unroll
    for (int p = 0; p < 2; p++) {
        int o = tid + p * 256;
        int d = o >> 3, c8 = (o & 7) * 8;
        uint32_t w[4];
#pragma unroll
        for (int j = 0; j < 4; j++)
            w[j] = pack2(__bfloat162float(t[c8 + 2 * j][d]),
                         __bfloat162float(t[c8 + 2 * j + 1][d]));
        *(uint4*)(dst + (size_t)d * NSEQ + c8) = make_uint4(w[0], w[1], w[2], w[3]);
    }
}

// ---------------- Attention: FA2-style, single pass, no max subtraction ------
// CTA: 128 q rows, 4 warps (32 q rows each). KV chunks of 64.
__global__ __launch_bounds__(128) void attn_kernel() {
    __shared__ char smem[32768];   // Q 16K @0, K 8K @16384, V^T 8K @24576
    int tid = threadIdx.x, warp = tid >> 5, lane = tid & 31;
    int q0 = blockIdx.x * 128, bh = blockIdx.y;

    const bf16* Qg = g_q + (size_t)bh * NSEQ * HDIM;
    const bf16* Kg = g_k + (size_t)bh * NSEQ * HDIM;
    const bf16* Vt = g_vt + (size_t)bh * HDIM * NSEQ;
    uint32_t sb = smem_u32(smem);

    // load Q tile [128][64]
#pragma unroll
    for (int p = 0; p < 8; p++) {
        int idx = tid + p * 128;
        int r = idx >> 3, ch = idx & 7;
        *(uint4*)(smem + row128(r, ch * 16)) =
            *(const uint4*)(Qg + (size_t)(q0 + r) * HDIM + ch * 8);
    }
    __syncthreads();

    // Q fragments, register-resident: 2 m-frags x 4 ksteps
    uint32_t qf[2][4][4];
    int arow = warp * 32 + (lane & 15);
    int acolx = (lane & 16) ? 16 : 0;
#pragma unroll
    for (int mf = 0; mf < 2; mf++)
#pragma unroll
        for (int ks = 0; ks < 4; ks++)
            ldsm4(qf[mf][ks][0], qf[mf][ks][1], qf[mf][ks][2], qf[mf][ks][3],
                  sb + row128(arow + mf * 16, ks * 32 + acolx));

    float of[2][8][4] = {};
    float lsum[2][2] = {};
    int brow0 = ((lane & 16) ? 8 : 0) + (lane & 7);
    int bcolx = (lane & 8) ? 16 : 0;

    for (int kt = 0; kt < NSEQ / 64; kt++) {
#pragma unroll
        for (int p = 0; p < 4; p++) {
            int idx = tid + p * 128;
            int r = idx >> 3, ch = idx & 7;
            uint32_t sw = row128(r, ch * 16);
            *(uint4*)(smem + 16384 + sw) =
                *(const uint4*)(Kg + (size_t)(kt * 64 + r) * HDIM + ch * 8);
            *(uint4*)(smem + 24576 + sw) =
                *(const uint4*)(Vt + (size_t)r * NSEQ + kt * 64 + ch * 8);
        }
        __syncthreads();

        // S = Q @ K^T : 32q x 64kv per warp
        float sf[2][8][4] = {};
#pragma unroll
        for (int ks = 0; ks < 4; ks++) {
            uint32_t bfr[8][2];
#pragma unroll
            for (int j = 0; j < 8; j += 2)
                ldsm4(bfr[j][0], bfr[j][1], bfr[j + 1][0], bfr[j + 1][1],
                      sb + 16384 + row128(brow0 + j * 8, ks * 32 + bcolx));
#pragma unroll
            for (int mf = 0; mf < 2; mf++)
#pragma unroll
                for (int nf = 0; nf < 8; nf++)
                    mma16816(sf[mf][nf], qf[mf][ks], bfr[nf]);
        }

        // P = exp(S) (unnormalized) -> A-fragments, accumulate l
        uint32_t pf[2][4][4];
#pragma unroll
        for (int mf = 0; mf < 2; mf++)
#pragma unroll
            for (int j = 0; j < 4; j++) {
                float e00 = __expf(sf[mf][2 * j][0]),     e01 = __expf(sf[mf][2 * j][1]);
                float e02 = __expf(sf[mf][2 * j][2]),     e03 = __expf(sf[mf][2 * j][3]);
                float e10 = __expf(sf[mf][2 * j + 1][0]), e11 = __expf(sf[mf][2 * j + 1][1]);
                float e12 = __expf(sf[mf][2 * j + 1][2]), e13 = __expf(sf[mf][2 * j + 1][3]);
                pf[mf][j][0] = pack2(e00, e01);
                pf[mf][j][1] = pack2(e02, e03);
                pf[mf][j][2] = pack2(e10, e11);
                pf[mf][j][3] = pack2(e12, e13);
                lsum[mf][0] += e00 + e01 + e10 + e11;
                lsum[mf][1] += e02 + e03 + e12 + e13;
            }

        // O += P @ V : B from V^T [d][kv]
#pragma unroll
        for (int ks = 0; ks < 4; ks++) {
            uint32_t bfr[8][2];
#pragma unroll
            for (int j = 0; j < 8; j += 2)
                ldsm4(bfr[j][0], bfr[j][1], bfr[j + 1][0], bfr[j + 1][1],
                      sb + 24576 + row128(brow0 + j * 8, ks * 32 + bcolx));
#pragma unroll
            for (int mf = 0; mf < 2; mf++)
#pragma unroll
                for (int nf = 0; nf < 8; nf++)
                    mma16816(of[mf][nf], pf[mf][ks], bfr[nf]);
        }
        __syncthreads();
    }

    // reduce l across the quad (4 lanes sharing a row), scale, store
    float scale[2][2];
#pragma unroll
    for (int mf = 0; mf < 2; mf++)
#pragma unroll
        for (int h = 0; h < 2; h++) {
            float l = lsum[mf][h];
            l += __shfl_xor_sync(~0u, l, 1);
            l += __shfl_xor_sync(~0u, l, 2);
            scale[mf][h] = ATT_SCALE / l;
        }
    int batch = bh / NHEADS, head = bh % NHEADS;
#pragma unroll
    for (int mf = 0; mf < 2; mf++) {
        int r0 = q0 + warp * 32 + mf * 16 + (lane >> 2);
#pragma unroll
        for (int nf = 0; nf < 8; nf++) {
            int d = nf * 8 + 2 * (lane & 3);
            bf16* D = g_vals + ((size_t)(batch * NSEQ + r0)) * TD + head * HDIM + d;
            *(uint32_t*)D = pack2(of[mf][nf][0] * scale[mf][0], of[mf][nf][1] * scale[mf][0]);
            *(uint32_t*)(D + (size_t)8 * TD) =
                pack2(of[mf][nf][2] * scale[mf][1], of[mf][nf][3] * scale[mf][1]);
        }
    }
}

// ---------------- Output projection: out = vals @ Wo + bo + x ----------------
__global__ __launch_bounds__(256) void out_kernel(const float* __restrict__ bo,
                                                  const float* __restrict__ x,
                                                  float* __restrict__ out) {
    __shared__ char smem[32768];
    int m0 = blockIdx.x * 128, n0 = blockIdx.y * 128;
    float c[4][4][4] = {};
    gemm128(g_vals, g_wt[3], smem, c, m0, n0);

    int tid = threadIdx.x, warp = tid >> 5, lane = tid & 31;
    int wm = (warp >> 2) * 64, wn = (warp & 3) * 32;
#pragma unroll
    for (int mf = 0; mf < 4; mf++) {
        int row = m0 + wm + mf * 16 + (lane >> 2);
#pragma unroll
        for (int nf = 0; nf < 4; nf++) {
            int col = n0 + wn + nf * 8 + 2 * (lane & 3);
            float2 bv = *(const float2*)(bo + col);
            size_t off0 = (size_t)row * TD + col;
            size_t off1 = (size_t)(row + 8) * TD + col;
            float2 x0 = *(const float2*)(x + off0);
            float2 x1 = *(const float2*)(x + off1);
            float2 o0 = make_float2(c[mf][nf][0] + bv.x + x0.x, c[mf][nf][1] + bv.y + x0.y);
            float2 o1 = make_float2(c[mf][nf][2] + bv.x + x1.x, c[mf][nf][3] + bv.y + x1.y);
            *(float2*)(out + off0) = o0;
            *(float2*)(out + off1) = o1;
        }
    }
}

// ---------------------------------------------------------------------------
extern "C" void kernel_launch(void* const* d_in, const int* in_sizes, int n_in,
                              void* d_out, int out_size) {
    (void)in_sizes; (void)n_in; (void)out_size;
    const float* x     = (const float*)d_in[0];
    const float* Wq    = (const float*)d_in[1];
    const float* Wk    = (const float*)d_in[2];
    const float* Wv    = (const float*)d_in[3];
    const float* Wo    = (const float*)d_in[4];
    const float* bo    = (const float*)d_in[5];
    const float* gamma = (const float*)d_in[6];
    const float* beta  = (const float*)d_in[7];
    float* out = (float*)d_out;

    ln_kernel<<<NROWS, 256>>>(x, gamma, beta);
    wtrans_kernel<<<dim3(TD / 32, TD / 32, 4), dim3(32, 8)>>>(Wq, Wk, Wv, Wo);
    qkv_kernel<<<dim3(NROWS / 128, TD / 128, 3), 256>>>();
    vtrans_kernel<<<dim3(NSEQ / 64, NBH), 256>>>();
    attn_kernel<<<dim3(NSEQ / 128, NBH), 128>>>();
    out_kernel<<<dim3(NROWS / 128, TD / 128), 256>>>(bo, x, out);
}

// round 6
// speedup vs baseline: 7.5625x; 1.0807x over previous
#include <cuda_runtime.h>
#include <cuda_bf16.h>
#include <cstdint>

#define TD 768
#define NHEADS 12
#define HDIM 64
#define NSEQ 2048
#define NROWS 4096
#define NBH 24
#define ATT_SCALE 0.125f
#define LN_EPS 1e-5f

typedef __nv_bfloat16 bf16;

__device__ bf16 g_h[(size_t)NROWS * TD];
__device__ bf16 g_wt[4][(size_t)TD * TD];            // W^T [n][k]
__device__ bf16 g_q[(size_t)NBH * NSEQ * HDIM];
__device__ bf16 g_k[(size_t)NBH * NSEQ * HDIM];
__device__ bf16 g_v[(size_t)NBH * NSEQ * HDIM];
__device__ bf16 g_vt[(size_t)NBH * HDIM * NSEQ];     // V^T [bh][d][seq]
__device__ bf16 g_vals[(size_t)NROWS * TD];

// ---------------- helpers ----------------
__device__ __forceinline__ uint32_t smem_u32(const void* p) {
    uint32_t a;
    asm("{ .reg .u64 t; cvta.to.shared.u64 t, %1; cvt.u32.u64 %0, t; }" : "=r"(a) : "l"(p));
    return a;
}
__device__ __forceinline__ uint32_t row128(int r, int cb) {
    uint32_t o = (uint32_t)(r * 128 + cb);
    return o ^ ((o >> 3) & 0x70);
}
__device__ __forceinline__ uint32_t pack2(float a, float b) {
    return (uint32_t)__bfloat16_as_ushort(__float2bfloat16_rn(a)) |
           ((uint32_t)__bfloat16_as_ushort(__float2bfloat16_rn(b)) << 16);
}
__device__ __forceinline__ void ldsm4(uint32_t& r0, uint32_t& r1, uint32_t& r2, uint32_t& r3,
                                      uint32_t addr) {
    asm volatile("ldmatrix.sync.aligned.m8n8.x4.shared.b16 {%0,%1,%2,%3}, [%4];"
        : "=r"(r0), "=r"(r1), "=r"(r2), "=r"(r3) : "r"(addr));
}
__device__ __forceinline__ void mma16816(float* c, const uint32_t* a, const uint32_t* b) {
    asm volatile("mma.sync.aligned.m16n8k16.row.col.f32.bf16.bf16.f32 "
        "{%0,%1,%2,%3}, {%4,%5,%6,%7}, {%8,%9}, {%0,%1,%2,%3};"
        : "+f"(c[0]), "+f"(c[1]), "+f"(c[2]), "+f"(c[3])
        : "r"(a[0]), "r"(a[1]), "r"(a[2]), "r"(a[3]), "r"(b[0]), "r"(b[1]));
}
#define CP16(dst, src) asm volatile("cp.async.cg.shared.global [%0], [%1], 16;" :: "r"(dst), "l"(src))
#define CP_COMMIT()    asm volatile("cp.async.commit_group;")
#define CP_WAIT0()     asm volatile("cp.async.wait_group 0;")
#define CP_WAIT1()     asm volatile("cp.async.wait_group 1;")

// ---------------- LayerNorm -> bf16 ----------------
__global__ __launch_bounds__(256) void ln_kernel(const float* __restrict__ x,
                                                 const float* __restrict__ gamma,
                                                 const float* __restrict__ beta) {
    int row = blockIdx.x;
    const float* xr = x + (size_t)row * TD;
    float v[3], sum = 0.f, sq = 0.f;
#pragma unroll
    for (int p = 0; p < 3; p++) {
        v[p] = xr[threadIdx.x + p * 256];
        sum += v[p]; sq += v[p] * v[p];
    }
#pragma unroll
    for (int o = 16; o; o >>= 1) {
        sum += __shfl_xor_sync(~0u, sum, o);
        sq  += __shfl_xor_sync(~0u, sq, o);
    }
    __shared__ float ss[8], sv[8];
    int w = threadIdx.x >> 5, l = threadIdx.x & 31;
    if (l == 0) { ss[w] = sum; sv[w] = sq; }
    __syncthreads();
    if (w == 0) {
        sum = ss[l & 7]; sq = sv[l & 7];
#pragma unroll
        for (int o = 4; o; o >>= 1) {
            sum += __shfl_xor_sync(~0u, sum, o);
            sq  += __shfl_xor_sync(~0u, sq, o);
        }
        if (l == 0) { ss[0] = sum; sv[0] = sq; }
    }
    __syncthreads();
    float mean = ss[0] * (1.f / TD);
    float rstd = rsqrtf(sv[0] * (1.f / TD) - mean * mean + LN_EPS);
#pragma unroll
    for (int p = 0; p < 3; p++) {
        int i = threadIdx.x + p * 256;
        g_h[(size_t)row * TD + i] =
            __float2bfloat16_rn((v[p] - mean) * rstd * gamma[i] + beta[i]);
    }
}

// ---------------- Weight transpose: wt[n][k] = W[k][n] (bf16) ----------------
__global__ __launch_bounds__(256) void wtrans_kernel(const float* __restrict__ Wq,
                                                     const float* __restrict__ Wk,
                                                     const float* __restrict__ Wv,
                                                     const float* __restrict__ Wo) {
    int z = blockIdx.z;
    const float* W = (z == 0) ? Wq : (z == 1) ? Wk : (z == 2) ? Wv : Wo;
    __shared__ float t[32][33];
    int n0 = blockIdx.x * 32, k0 = blockIdx.y * 32;
    int tx = threadIdx.x, ty = threadIdx.y;
#pragma unroll
    for (int i = 0; i < 4; i++)
        t[ty + 8 * i][tx] = W[(size_t)(k0 + ty + 8 * i) * TD + n0 + tx];
    __syncthreads();
#pragma unroll
    for (int i = 0; i < 4; i++)
        g_wt[z][(size_t)(n0 + ty + 8 * i) * TD + k0 + tx] =
            __float2bfloat16_rn(t[tx][ty + 8 * i]);
}

// ---------------- core 128x128 GEMM mainloop (cp.async double-buffered) -----
// smem: stage s at s*32768 { A 16K, B 16K }. 256 threads, 8 warps 2x4.
__device__ __forceinline__ void gemm128(const bf16* __restrict__ A, const bf16* __restrict__ Bt,
                                        char* smem, float c[4][4][4], int m0, int n0) {
    int tid = threadIdx.x, warp = tid >> 5, lane = tid & 31;
    int wm = (warp >> 2) * 64, wn = (warp & 3) * 32;
    uint32_t sb = smem_u32(smem);
    int arow = wm + (lane & 15);
    int acolx = (lane & 16) ? 16 : 0;
    int brow0 = wn + ((lane & 16) ? 8 : 0) + (lane & 7);
    int bcolx = (lane & 8) ? 16 : 0;

    int lr = tid >> 3, lch = tid & 7;            // loader: rows tid/8 (+32 steps), chunk
    uint32_t lsw[4];
#pragma unroll
    for (int p = 0; p < 4; p++) lsw[p] = row128(lr + p * 32, lch * 16);

    // prologue: stage 0
#pragma unroll
    for (int p = 0; p < 4; p++) {
        int r = lr + p * 32;
        CP16(sb + lsw[p],         A  + (size_t)(m0 + r) * TD + lch * 8);
        CP16(sb + 16384 + lsw[p], Bt + (size_t)(n0 + r) * TD + lch * 8);
    }
    CP_COMMIT();

    for (int i = 0; i < 12; i++) {
        uint32_t stg = (uint32_t)(i & 1) * 32768;
        if (i < 11) {
            uint32_t nst = (uint32_t)((i + 1) & 1) * 32768;
#pragma unroll
            for (int p = 0; p < 4; p++) {
                int r = lr + p * 32;
                CP16(sb + nst + lsw[p],         A  + (size_t)(m0 + r) * TD + (i + 1) * 64 + lch * 8);
                CP16(sb + nst + 16384 + lsw[p], Bt + (size_t)(n0 + r) * TD + (i + 1) * 64 + lch * 8);
            }
            CP_COMMIT();
            CP_WAIT1();
        } else {
            CP_WAIT0();
        }
        __syncthreads();
#pragma unroll
        for (int ks = 0; ks < 4; ks++) {
            uint32_t af[4][4], bfr[4][2];
#pragma unroll
            for (int mf = 0; mf < 4; mf++)
                ldsm4(af[mf][0], af[mf][1], af[mf][2], af[mf][3],
                      sb + stg + row128(arow + mf * 16, ks * 32 + acolx));
#pragma unroll
            for (int j = 0; j < 4; j += 2)
                ldsm4(bfr[j][0], bfr[j][1], bfr[j + 1][0], bfr[j + 1][1],
                      sb + stg + 16384 + row128(brow0 + j * 8, ks * 32 + bcolx));
#pragma unroll
            for (int mf = 0; mf < 4; mf++)
#pragma unroll
                for (int nf = 0; nf < 4; nf++)
                    mma16816(c[mf][nf], af[mf], bfr[nf]);
        }
        __syncthreads();
    }
}

// ---------------- QKV GEMM ----------------
#define GEMM_SMEM 65536
__global__ __launch_bounds__(256) void qkv_kernel() {
    extern __shared__ char smem[];
    int z = blockIdx.z;
    int m0 = blockIdx.x * 128, n0 = blockIdx.y * 128;
    float c[4][4][4] = {};
    gemm128(g_h, g_wt[z], smem, c, m0, n0);

    bf16* G = (z == 0) ? g_q : (z == 1) ? g_k : g_v;
    int tid = threadIdx.x, warp = tid >> 5, lane = tid & 31;
    int wm = (warp >> 2) * 64, wn = (warp & 3) * 32;
#pragma unroll
    for (int mf = 0; mf < 4; mf++) {
        int row = m0 + wm + mf * 16 + (lane >> 2);
        int batch = row >> 11, seq = row & (NSEQ - 1);
#pragma unroll
        for (int nf = 0; nf < 4; nf++) {
            int col = n0 + wn + nf * 8 + 2 * (lane & 3);
            int head = col >> 6, d = col & 63;
            bf16* D = G + ((size_t)(batch * NHEADS + head) * NSEQ + seq) * HDIM + d;
            *(uint32_t*)D = pack2(c[mf][nf][0], c[mf][nf][1]);
            *(uint32_t*)(D + 8 * HDIM) = pack2(c[mf][nf][2], c[mf][nf][3]);
        }
    }
}

// ---------------- V transpose: g_vt[bh][d][s] = g_v[bh][s][d] ----------------
__global__ __launch_bounds__(256) void vtrans_kernel() {
    int bh = blockIdx.y, s0 = blockIdx.x * 64;
    __shared__ bf16 t[64][72];
    const bf16* src = g_v + ((size_t)bh * NSEQ + s0) * HDIM;
    int tid = threadIdx.x;
#pragma unroll
    for (int p = 0; p < 2; p++) {
        int o = tid + p * 256;
        int r = o >> 3, s = o & 7;
        *(uint4*)&t[r][s * 8] = *(const uint4*)(src + (size_t)r * HDIM + s * 8);
    }
    __syncthreads();
    bf16* dst = g_vt + (size_t)bh * HDIM * NSEQ + s0;
#pragma unroll
    for (int p = 0; p < 2; p++) {
        int o = tid + p * 256;
        int d = o >> 3, c8 = (o & 7) * 8;
        uint32_t w[4];
#pragma unroll
        for (int j = 0; j < 4; j++)
            w[j] = pack2(__bfloat162float(t[c8 + 2 * j][d]),
                         __bfloat162float(t[c8 + 2 * j + 1][d]));
        *(uint4*)(dst + (size_t)d * NSEQ + c8) = make_uint4(w[0], w[1], w[2], w[3]);
    }
}

// ---------------- Attention: FA2-style, 8 warps x 16 q rows, cp.async -------
// smem: Q 16K @0 | K 2x8K @16384 | V^T 2x8K @32768  (48KB static)
__global__ __launch_bounds__(256) void attn_kernel() {
    __shared__ char smem[49152];
    int tid = threadIdx.x, warp = tid >> 5, lane = tid & 31;
    int q0 = blockIdx.x * 128, bh = blockIdx.y;

    const bf16* Qg = g_q + (size_t)bh * NSEQ * HDIM;
    const bf16* Kg = g_k + (size_t)bh * NSEQ * HDIM;
    const bf16* Vt = g_vt + (size_t)bh * HDIM * NSEQ;
    uint32_t sb = smem_u32(smem);

    // Q tile [128][64] via cp.async (group 0)
#pragma unroll
    for (int p = 0; p < 4; p++) {
        int idx = tid + p * 256;
        int r = idx >> 3, ch = idx & 7;
        CP16(sb + row128(r, ch * 16), Qg + (size_t)(q0 + r) * HDIM + ch * 8);
    }
    CP_COMMIT();

    int kr = tid >> 3, kch = tid & 7;   // K/V loader indices (2 rows each)
    uint32_t ksw[2];
    ksw[0] = row128(kr, kch * 16);
    ksw[1] = row128(kr + 32, kch * 16);
    // K/V tile kt=0 into buf 0 (group 1)
#pragma unroll
    for (int p = 0; p < 2; p++) {
        int r = kr + p * 32;
        CP16(sb + 16384 + ksw[p], Kg + (size_t)r * HDIM + kch * 8);
        CP16(sb + 32768 + ksw[p], Vt + (size_t)r * NSEQ + kch * 8);
    }
    CP_COMMIT();

    CP_WAIT1();          // Q ready
    __syncthreads();

    // Q fragments: 16 rows per warp, 4 ksteps
    uint32_t qf[4][4];
    int arow = warp * 16 + (lane & 15);
    int acolx = (lane & 16) ? 16 : 0;
#pragma unroll
    for (int ks = 0; ks < 4; ks++)
        ldsm4(qf[ks][0], qf[ks][1], qf[ks][2], qf[ks][3],
              sb + row128(arow, ks * 32 + acolx));

    float of[8][4] = {};
    float lsum[2] = {};
    int brow0 = ((lane & 16) ? 8 : 0) + (lane & 7);
    int bcolx = (lane & 8) ? 16 : 0;

    for (int kt = 0; kt < NSEQ / 64; kt++) {
        uint32_t stg = (uint32_t)(kt & 1) * 8192;
        if (kt < NSEQ / 64 - 1) {
            uint32_t nst = (uint32_t)((kt + 1) & 1) * 8192;
#pragma unroll
            for (int p = 0; p < 2; p++) {
                int r = kr + p * 32;
                CP16(sb + 16384 + nst + ksw[p], Kg + (size_t)((kt + 1) * 64 + r) * HDIM + kch * 8);
                CP16(sb + 32768 + nst + ksw[p], Vt + (size_t)r * NSEQ + (kt + 1) * 64 + kch * 8);
            }
            CP_COMMIT();
            CP_WAIT1();
        } else {
            CP_WAIT0();
        }
        __syncthreads();

        // S = Q @ K^T : 16q x 64kv per warp
        float sf[8][4] = {};
#pragma unroll
        for (int ks = 0; ks < 4; ks++) {
            uint32_t bfr[8][2];
#pragma unroll
            for (int j = 0; j < 8; j += 2)
                ldsm4(bfr[j][0], bfr[j][1], bfr[j + 1][0], bfr[j + 1][1],
                      sb + 16384 + stg + row128(brow0 + j * 8, ks * 32 + bcolx));
#pragma unroll
            for (int nf = 0; nf < 8; nf++)
                mma16816(sf[nf], qf[ks], bfr[nf]);
        }

        // P = exp(S) (unnormalized) -> A-fragments, accumulate l
        uint32_t pf[4][4];
#pragma unroll
        for (int j = 0; j < 4; j++) {
            float e00 = __expf(sf[2 * j][0]),     e01 = __expf(sf[2 * j][1]);
            float e02 = __expf(sf[2 * j][2]),     e03 = __expf(sf[2 * j][3]);
            float e10 = __expf(sf[2 * j + 1][0]), e11 = __expf(sf[2 * j + 1][1]);
            float e12 = __expf(sf[2 * j + 1][2]), e13 = __expf(sf[2 * j + 1][3]);
            pf[j][0] = pack2(e00, e01);
            pf[j][1] = pack2(e02, e03);
            pf[j][2] = pack2(e10, e11);
            pf[j][3] = pack2(e12, e13);
            lsum[0] += e00 + e01 + e10 + e11;
            lsum[1] += e02 + e03 + e12 + e13;
        }

        // O += P @ V : B from V^T [d][kv]
#pragma unroll
        for (int ks = 0; ks < 4; ks++) {
            uint32_t bfr[8][2];
#pragma unroll
            for (int j = 0; j < 8; j += 2)
                ldsm4(bfr[j][0], bfr[j][1], bfr[j + 1][0], bfr[j + 1][1],
                      sb + 32768 + stg + row128(brow0 + j * 8, ks * 32 + bcolx));
#pragma unroll
            for (int nf = 0; nf < 8; nf++)
                mma16816(of[nf], pf[ks], bfr[nf]);
        }
        __syncthreads();
    }

    // reduce l across the quad, scale, store
    float scale[2];
#pragma unroll
    for (int h = 0; h < 2; h++) {
        float l = lsum[h];
        l += __shfl_xor_sync(~0u, l, 1);
        l += __shfl_xor_sync(~0u, l, 2);
        scale[h] = ATT_SCALE / l;
    }
    int batch = bh / NHEADS, head = bh % NHEADS;
    int r0 = q0 + warp * 16 + (lane >> 2);
#pragma unroll
    for (int nf = 0; nf < 8; nf++) {
        int d = nf * 8 + 2 * (lane & 3);
        bf16* D = g_vals + ((size_t)(batch * NSEQ + r0)) * TD + head * HDIM + d;
        *(uint32_t*)D = pack2(of[nf][0] * scale[0], of[nf][1] * scale[0]);
        *(uint32_t*)(D + (size_t)8 * TD) = pack2(of[nf][2] * scale[1], of[nf][3] * scale[1]);
    }
}

// ---------------- Output projection: out = vals @ Wo + bo + x ----------------
__global__ __launch_bounds__(256) void out_kernel(const float* __restrict__ bo,
                                                  const float* __restrict__ x,
                                                  float* __restrict__ out) {
    extern __shared__ char smem[];
    int m0 = blockIdx.x * 128, n0 = blockIdx.y * 128;
    float c[4][4][4] = {};
    gemm128(g_vals, g_wt[3], smem, c, m0, n0);

    int tid = threadIdx.x, warp = tid >> 5, lane = tid & 31;
    int wm = (warp >> 2) * 64, wn = (warp & 3) * 32;
#pragma unroll
    for (int mf = 0; mf < 4; mf++) {
        int row = m0 + wm + mf * 16 + (lane >> 2);
#pragma unroll
        for (int nf = 0; nf < 4; nf++) {
            int col = n0 + wn + nf * 8 + 2 * (lane & 3);
            float2 bv = *(const float2*)(bo + col);
            size_t off0 = (size_t)row * TD + col;
            size_t off1 = (size_t)(row + 8) * TD + col;
            float2 x0 = *(const float2*)(x + off0);
            float2 x1 = *(const float2*)(x + off1);
            *(float2*)(out + off0) = make_float2(c[mf][nf][0] + bv.x + x0.x,
                                                 c[mf][nf][1] + bv.y + x0.y);
            *(float2*)(out + off1) = make_float2(c[mf][nf][2] + bv.x + x1.x,
                                                 c[mf][nf][3] + bv.y + x1.y);
        }
    }
}

// ---------------------------------------------------------------------------
extern "C" void kernel_launch(void* const* d_in, const int* in_sizes, int n_in,
                              void* d_out, int out_size) {
    (void)in_sizes; (void)n_in; (void)out_size;
    const float* x     = (const float*)d_in[0];
    const float* Wq    = (const float*)d_in[1];
    const float* Wk    = (const float*)d_in[2];
    const float* Wv    = (const float*)d_in[3];
    const float* Wo    = (const float*)d_in[4];
    const float* bo    = (const float*)d_in[5];
    const float* gamma = (const float*)d_in[6];
    const float* beta  = (const float*)d_in[7];
    float* out = (float*)d_out;

    cudaFuncSetAttribute(qkv_kernel, cudaFuncAttributeMaxDynamicSharedMemorySize, GEMM_SMEM);
    cudaFuncSetAttribute(out_kernel, cudaFuncAttributeMaxDynamicSharedMemorySize, GEMM_SMEM);

    ln_kernel<<<NROWS, 256>>>(x, gamma, beta);
    wtrans_kernel<<<dim3(TD / 32, TD / 32, 4), dim3(32, 8)>>>(Wq, Wk, Wv, Wo);
    qkv_kernel<<<dim3(NROWS / 128, TD / 128, 3), 256, GEMM_SMEM>>>();
    vtrans_kernel<<<dim3(NSEQ / 64, NBH), 256>>>();
    attn_kernel<<<dim3(NSEQ / 128, NBH), 256>>>();
    out_kernel<<<dim3(NROWS / 128, TD / 128), 256, GEMM_SMEM>>>(bo, x, out);
}

// round 7
// speedup vs baseline: 8.0653x; 1.0665x over previous
#include <cuda_runtime.h>
#include <cuda_bf16.h>
#include <cstdint>

#define TD 768
#define NHEADS 12
#define HDIM 64
#define NSEQ 2048
#define NROWS 4096
#define NBH 24
#define ATT_SCALE 0.125f
#define LN_EPS 1e-5f

typedef __nv_bfloat16 bf16;

__device__ bf16 g_h[(size_t)NROWS * TD];
__device__ bf16 g_wt[4][(size_t)TD * TD];            // W^T [n][k]
__device__ bf16 g_q[(size_t)NBH * NSEQ * HDIM];
__device__ bf16 g_k[(size_t)NBH * NSEQ * HDIM];
__device__ bf16 g_vt[(size_t)NBH * HDIM * NSEQ];     // V^T [bh][d][seq]
__device__ bf16 g_vals[(size_t)NROWS * TD];

// ---------------- helpers ----------------
__device__ __forceinline__ uint32_t smem_u32(const void* p) {
    uint32_t a;
    asm("{ .reg .u64 t; cvta.to.shared.u64 t, %1; cvt.u32.u64 %0, t; }" : "=r"(a) : "l"(p));
    return a;
}
__device__ __forceinline__ uint32_t row128(int r, int cb) {
    uint32_t o = (uint32_t)(r * 128 + cb);
    return o ^ ((o >> 3) & 0x70);
}
__device__ __forceinline__ uint32_t pack2(float a, float b) {
    return (uint32_t)__bfloat16_as_ushort(__float2bfloat16_rn(a)) |
           ((uint32_t)__bfloat16_as_ushort(__float2bfloat16_rn(b)) << 16);
}
__device__ __forceinline__ void ldsm4(uint32_t& r0, uint32_t& r1, uint32_t& r2, uint32_t& r3,
                                      uint32_t addr) {
    asm volatile("ldmatrix.sync.aligned.m8n8.x4.shared.b16 {%0,%1,%2,%3}, [%4];"
        : "=r"(r0), "=r"(r1), "=r"(r2), "=r"(r3) : "r"(addr));
}
__device__ __forceinline__ void mma16816(float* c, const uint32_t* a, const uint32_t* b) {
    asm volatile("mma.sync.aligned.m16n8k16.row.col.f32.bf16.bf16.f32 "
        "{%0,%1,%2,%3}, {%4,%5,%6,%7}, {%8,%9}, {%0,%1,%2,%3};"
        : "+f"(c[0]), "+f"(c[1]), "+f"(c[2]), "+f"(c[3])
        : "r"(a[0]), "r"(a[1]), "r"(a[2]), "r"(a[3]), "r"(b[0]), "r"(b[1]));
}
#define CP16(dst, src) asm volatile("cp.async.cg.shared.global [%0], [%1], 16;" :: "r"(dst), "l"(src))
#define CP_COMMIT()    asm volatile("cp.async.commit_group;")
#define CP_WAIT0()     asm volatile("cp.async.wait_group 0;")
#define CP_WAIT1()     asm volatile("cp.async.wait_group 1;")

// ---------------- LayerNorm -> bf16 ----------------
__global__ __launch_bounds__(256) void ln_kernel(const float* __restrict__ x,
                                                 const float* __restrict__ gamma,
                                                 const float* __restrict__ beta) {
    int row = blockIdx.x;
    const float* xr = x + (size_t)row * TD;
    float v[3], sum = 0.f, sq = 0.f;
#pragma unroll
    for (int p = 0; p < 3; p++) {
        v[p] = xr[threadIdx.x + p * 256];
        sum += v[p]; sq += v[p] * v[p];
    }
#pragma unroll
    for (int o = 16; o; o >>= 1) {
        sum += __shfl_xor_sync(~0u, sum, o);
        sq  += __shfl_xor_sync(~0u, sq, o);
    }
    __shared__ float ss[8], sv[8];
    int w = threadIdx.x >> 5, l = threadIdx.x & 31;
    if (l == 0) { ss[w] = sum; sv[w] = sq; }
    __syncthreads();
    if (w == 0) {
        sum = ss[l & 7]; sq = sv[l & 7];
#pragma unroll
        for (int o = 4; o; o >>= 1) {
            sum += __shfl_xor_sync(~0u, sum, o);
            sq  += __shfl_xor_sync(~0u, sq, o);
        }
        if (l == 0) { ss[0] = sum; sv[0] = sq; }
    }
    __syncthreads();
    float mean = ss[0] * (1.f / TD);
    float rstd = rsqrtf(sv[0] * (1.f / TD) - mean * mean + LN_EPS);
#pragma unroll
    for (int p = 0; p < 3; p++) {
        int i = threadIdx.x + p * 256;
        g_h[(size_t)row * TD + i] =
            __float2bfloat16_rn((v[p] - mean) * rstd * gamma[i] + beta[i]);
    }
}

// ---------------- Weight transpose: wt[n][k] = W[k][n] (bf16) ----------------
__global__ __launch_bounds__(256) void wtrans_kernel(const float* __restrict__ Wq,
                                                     const float* __restrict__ Wk,
                                                     const float* __restrict__ Wv,
                                                     const float* __restrict__ Wo) {
    int z = blockIdx.z;
    const float* W = (z == 0) ? Wq : (z == 1) ? Wk : (z == 2) ? Wv : Wo;
    __shared__ float t[32][33];
    int n0 = blockIdx.x * 32, k0 = blockIdx.y * 32;
    int tx = threadIdx.x, ty = threadIdx.y;
#pragma unroll
    for (int i = 0; i < 4; i++)
        t[ty + 8 * i][tx] = W[(size_t)(k0 + ty + 8 * i) * TD + n0 + tx];
    __syncthreads();
#pragma unroll
    for (int i = 0; i < 4; i++)
        g_wt[z][(size_t)(n0 + ty + 8 * i) * TD + k0 + tx] =
            __float2bfloat16_rn(t[tx][ty + 8 * i]);
}

// ---------------- core 128x128 GEMM mainloop (cp.async double-buffered) -----
__device__ __forceinline__ void gemm128(const bf16* __restrict__ A, const bf16* __restrict__ Bt,
                                        char* smem, float c[4][4][4], int m0, int n0) {
    int tid = threadIdx.x, warp = tid >> 5, lane = tid & 31;
    int wm = (warp >> 2) * 64, wn = (warp & 3) * 32;
    uint32_t sb = smem_u32(smem);
    int arow = wm + (lane & 15);
    int acolx = (lane & 16) ? 16 : 0;
    int brow0 = wn + ((lane & 16) ? 8 : 0) + (lane & 7);
    int bcolx = (lane & 8) ? 16 : 0;

    int lr = tid >> 3, lch = tid & 7;
    uint32_t lsw[4];
#pragma unroll
    for (int p = 0; p < 4; p++) lsw[p] = row128(lr + p * 32, lch * 16);

#pragma unroll
    for (int p = 0; p < 4; p++) {
        int r = lr + p * 32;
        CP16(sb + lsw[p],         A  + (size_t)(m0 + r) * TD + lch * 8);
        CP16(sb + 16384 + lsw[p], Bt + (size_t)(n0 + r) * TD + lch * 8);
    }
    CP_COMMIT();

    for (int i = 0; i < 12; i++) {
        uint32_t stg = (uint32_t)(i & 1) * 32768;
        if (i < 11) {
            uint32_t nst = (uint32_t)((i + 1) & 1) * 32768;
#pragma unroll
            for (int p = 0; p < 4; p++) {
                int r = lr + p * 32;
                CP16(sb + nst + lsw[p],         A  + (size_t)(m0 + r) * TD + (i + 1) * 64 + lch * 8);
                CP16(sb + nst + 16384 + lsw[p], Bt + (size_t)(n0 + r) * TD + (i + 1) * 64 + lch * 8);
            }
            CP_COMMIT();
            CP_WAIT1();
        } else {
            CP_WAIT0();
        }
        __syncthreads();
#pragma unroll
        for (int ks = 0; ks < 4; ks++) {
            uint32_t af[4][4], bfr[4][2];
#pragma unroll
            for (int mf = 0; mf < 4; mf++)
                ldsm4(af[mf][0], af[mf][1], af[mf][2], af[mf][3],
                      sb + stg + row128(arow + mf * 16, ks * 32 + acolx));
#pragma unroll
            for (int j = 0; j < 4; j += 2)
                ldsm4(bfr[j][0], bfr[j][1], bfr[j + 1][0], bfr[j + 1][1],
                      sb + stg + 16384 + row128(brow0 + j * 8, ks * 32 + bcolx));
#pragma unroll
            for (int mf = 0; mf < 4; mf++)
#pragma unroll
                for (int nf = 0; nf < 4; nf++)
                    mma16816(c[mf][nf], af[mf], bfr[nf]);
        }
        __syncthreads();
    }
}

// ---------------- QKV GEMM (V written transposed via smem bounce) -----------
#define GEMM_SMEM 65536
__global__ __launch_bounds__(256) void qkv_kernel() {
    extern __shared__ char smem[];
    int z = blockIdx.z;
    int m0 = blockIdx.x * 128, n0 = blockIdx.y * 128;
    float c[4][4][4] = {};
    gemm128(g_h, g_wt[z], smem, c, m0, n0);

    int tid = threadIdx.x, warp = tid >> 5, lane = tid & 31;
    int wm = (warp >> 2) * 64, wn = (warp & 3) * 32;

    if (z < 2) {
        bf16* G = (z == 0) ? g_q : g_k;
#pragma unroll
        for (int mf = 0; mf < 4; mf++) {
            int row = m0 + wm + mf * 16 + (lane >> 2);
            int batch = row >> 11, seq = row & (NSEQ - 1);
#pragma unroll
            for (int nf = 0; nf < 4; nf++) {
                int col = n0 + wn + nf * 8 + 2 * (lane & 3);
                int head = col >> 6, d = col & 63;
                bf16* D = G + ((size_t)(batch * NHEADS + head) * NSEQ + seq) * HDIM + d;
                *(uint32_t*)D = pack2(c[mf][nf][0], c[mf][nf][1]);
                *(uint32_t*)(D + 8 * HDIM) = pack2(c[mf][nf][2], c[mf][nf][3]);
            }
        }
    } else {
        // V: transpose in smem, write g_vt[bh][d][seq] directly
        bf16* ts = (bf16*)smem;     // [128 cols n][136 pitch m]
        __syncthreads();            // gemm128 left smem free
#pragma unroll
        for (int mf = 0; mf < 4; mf++) {
            int lr0 = wm + mf * 16 + (lane >> 2);
#pragma unroll
            for (int nf = 0; nf < 4; nf++) {
                int lc = wn + nf * 8 + 2 * (lane & 3);
                ts[(size_t)lc * 136 + lr0]           = __float2bfloat16_rn(c[mf][nf][0]);
                ts[(size_t)(lc + 1) * 136 + lr0]     = __float2bfloat16_rn(c[mf][nf][1]);
                ts[(size_t)lc * 136 + lr0 + 8]       = __float2bfloat16_rn(c[mf][nf][2]);
                ts[(size_t)(lc + 1) * 136 + lr0 + 8] = __float2bfloat16_rn(c[mf][nf][3]);
            }
        }
        __syncthreads();
        int n = tid >> 1, mh = (tid & 1) * 64;
        int col = n0 + n, head = col >> 6, d = col & 63;
        int batch = blockIdx.x >> 4;
        int seq0 = (m0 & (NSEQ - 1)) + mh;
        bf16* D = g_vt + ((size_t)(batch * NHEADS + head) * HDIM + d) * NSEQ + seq0;
#pragma unroll
        for (int s = 0; s < 8; s++)
            *(uint4*)(D + s * 8) = *(uint4*)&ts[(size_t)n * 136 + mh + s * 8];
    }
}

// ---------------- Attention: FA2-style, 8 warps x 16 q rows, 2 CTA/SM -------
// smem: Q 16K @0 | K 2x8K @16384 | V^T 2x8K @32768  (48KB static)
__global__ __launch_bounds__(256, 2) void attn_kernel() {
    __shared__ char smem[49152];
    int tid = threadIdx.x, warp = tid >> 5, lane = tid & 31;
    int q0 = blockIdx.x * 128, bh = blockIdx.y;

    const bf16* Qg = g_q + (size_t)bh * NSEQ * HDIM;
    const bf16* Kg = g_k + (size_t)bh * NSEQ * HDIM;
    const bf16* Vt = g_vt + (size_t)bh * HDIM * NSEQ;
    uint32_t sb = smem_u32(smem);

#pragma unroll
    for (int p = 0; p < 4; p++) {
        int idx = tid + p * 256;
        int r = idx >> 3, ch = idx & 7;
        CP16(sb + row128(r, ch * 16), Qg + (size_t)(q0 + r) * HDIM + ch * 8);
    }
    CP_COMMIT();

    int kr = tid >> 3, kch = tid & 7;
    uint32_t ksw[2];
    ksw[0] = row128(kr, kch * 16);
    ksw[1] = row128(kr + 32, kch * 16);
#pragma unroll
    for (int p = 0; p < 2; p++) {
        int r = kr + p * 32;
        CP16(sb + 16384 + ksw[p], Kg + (size_t)r * HDIM + kch * 8);
        CP16(sb + 32768 + ksw[p], Vt + (size_t)r * NSEQ + kch * 8);
    }
    CP_COMMIT();

    CP_WAIT1();
    __syncthreads();

    uint32_t qf[4][4];
    int arow = warp * 16 + (lane & 15);
    int acolx = (lane & 16) ? 16 : 0;
#pragma unroll
    for (int ks = 0; ks < 4; ks++)
        ldsm4(qf[ks][0], qf[ks][1], qf[ks][2], qf[ks][3],
              sb + row128(arow, ks * 32 + acolx));

    float of[8][4] = {};
    float lsum[2] = {};
    int brow0 = ((lane & 16) ? 8 : 0) + (lane & 7);
    int bcolx = (lane & 8) ? 16 : 0;

    for (int kt = 0; kt < NSEQ / 64; kt++) {
        uint32_t stg = (uint32_t)(kt & 1) * 8192;
        if (kt < NSEQ / 64 - 1) {
            uint32_t nst = (uint32_t)((kt + 1) & 1) * 8192;
#pragma unroll
            for (int p = 0; p < 2; p++) {
                int r = kr + p * 32;
                CP16(sb + 16384 + nst + ksw[p], Kg + (size_t)((kt + 1) * 64 + r) * HDIM + kch * 8);
                CP16(sb + 32768 + nst + ksw[p], Vt + (size_t)r * NSEQ + (kt + 1) * 64 + kch * 8);
            }
            CP_COMMIT();
            CP_WAIT1();
        } else {
            CP_WAIT0();
        }
        __syncthreads();

        // S = Q @ K^T in two 32-kv halves (keeps register peak ~110)
        uint32_t pf[4][4];
#pragma unroll
        for (int half = 0; half < 2; half++) {
            float sf[4][4] = {};
#pragma unroll
            for (int ks = 0; ks < 4; ks++) {
                uint32_t bfr[4][2];
#pragma unroll
                for (int j = 0; j < 4; j += 2)
                    ldsm4(bfr[j][0], bfr[j][1], bfr[j + 1][0], bfr[j + 1][1],
                          sb + 16384 + stg + row128(brow0 + half * 32 + j * 8, ks * 32 + bcolx));
#pragma unroll
                for (int nf = 0; nf < 4; nf++)
                    mma16816(sf[nf], qf[ks], bfr[nf]);
            }
#pragma unroll
            for (int j = 0; j < 2; j++) {
                float e00 = __expf(sf[2 * j][0]),     e01 = __expf(sf[2 * j][1]);
                float e02 = __expf(sf[2 * j][2]),     e03 = __expf(sf[2 * j][3]);
                float e10 = __expf(sf[2 * j + 1][0]), e11 = __expf(sf[2 * j + 1][1]);
                float e12 = __expf(sf[2 * j + 1][2]), e13 = __expf(sf[2 * j + 1][3]);
                int pj = half * 2 + j;
                pf[pj][0] = pack2(e00, e01);
                pf[pj][1] = pack2(e02, e03);
                pf[pj][2] = pack2(e10, e11);
                pf[pj][3] = pack2(e12, e13);
                lsum[0] += e00 + e01 + e10 + e11;
                lsum[1] += e02 + e03 + e12 + e13;
            }
        }

        // O += P @ V : B from V^T [d][kv]
#pragma unroll
        for (int ks = 0; ks < 4; ks++) {
            uint32_t bfr[8][2];
#pragma unroll
            for (int j = 0; j < 8; j += 2)
                ldsm4(bfr[j][0], bfr[j][1], bfr[j + 1][0], bfr[j + 1][1],
                      sb + 32768 + stg + row128(brow0 + j * 8, ks * 32 + bcolx));
#pragma unroll
            for (int nf = 0; nf < 8; nf++)
                mma16816(of[nf], pf[ks], bfr[nf]);
        }
        __syncthreads();
    }

    float scale[2];
#pragma unroll
    for (int h = 0; h < 2; h++) {
        float l = lsum[h];
        l += __shfl_xor_sync(~0u, l, 1);
        l += __shfl_xor_sync(~0u, l, 2);
        scale[h] = ATT_SCALE / l;
    }
    int batch = bh / NHEADS, head = bh % NHEADS;
    int r0 = q0 + warp * 16 + (lane >> 2);
#pragma unroll
    for (int nf = 0; nf < 8; nf++) {
        int d = nf * 8 + 2 * (lane & 3);
        bf16* D = g_vals + ((size_t)(batch * NSEQ + r0)) * TD + head * HDIM + d;
        *(uint32_t*)D = pack2(of[nf][0] * scale[0], of[nf][1] * scale[0]);
        *(uint32_t*)(D + (size_t)8 * TD) = pack2(of[nf][2] * scale[1], of[nf][3] * scale[1]);
    }
}

// ---------------- Output projection: out = vals @ Wo + bo + x ----------------
__global__ __launch_bounds__(256) void out_kernel(const float* __restrict__ bo,
                                                  const float* __restrict__ x,
                                                  float* __restrict__ out) {
    extern __shared__ char smem[];
    int m0 = blockIdx.x * 128, n0 = blockIdx.y * 128;
    float c[4][4][4] = {};
    gemm128(g_vals, g_wt[3], smem, c, m0, n0);

    int tid = threadIdx.x, warp = tid >> 5, lane = tid & 31;
    int wm = (warp >> 2) * 64, wn = (warp & 3) * 32;
#pragma unroll
    for (int mf = 0; mf < 4; mf++) {
        int row = m0 + wm + mf * 16 + (lane >> 2);
#pragma unroll
        for (int nf = 0; nf < 4; nf++) {
            int col = n0 + wn + nf * 8 + 2 * (lane & 3);
            float2 bv = *(const float2*)(bo + col);
            size_t off0 = (size_t)row * TD + col;
            size_t off1 = (size_t)(row + 8) * TD + col;
            float2 x0 = *(const float2*)(x + off0);
            float2 x1 = *(const float2*)(x + off1);
            *(float2*)(out + off0) = make_float2(c[mf][nf][0] + bv.x + x0.x,
                                                 c[mf][nf][1] + bv.y + x0.y);
            *(float2*)(out + off1) = make_float2(c[mf][nf][2] + bv.x + x1.x,
                                                 c[mf][nf][3] + bv.y + x1.y);
        }
    }
}

// ---------------------------------------------------------------------------
extern "C" void kernel_launch(void* const* d_in, const int* in_sizes, int n_in,
                              void* d_out, int out_size) {
    (void)in_sizes; (void)n_in; (void)out_size;
    const float* x     = (const float*)d_in[0];
    const float* Wq    = (const float*)d_in[1];
    const float* Wk    = (const float*)d_in[2];
    const float* Wv    = (const float*)d_in[3];
    const float* Wo    = (const float*)d_in[4];
    const float* bo    = (const float*)d_in[5];
    const float* gamma = (const float*)d_in[6];
    const float* beta  = (const float*)d_in[7];
    float* out = (float*)d_out;

    cudaFuncSetAttribute(qkv_kernel, cudaFuncAttributeMaxDynamicSharedMemorySize, GEMM_SMEM);
    cudaFuncSetAttribute(out_kernel, cudaFuncAttributeMaxDynamicSharedMemorySize, GEMM_SMEM);

    ln_kernel<<<NROWS, 256>>>(x, gamma, beta);
    wtrans_kernel<<<dim3(TD / 32, TD / 32, 4), dim3(32, 8)>>>(Wq, Wk, Wv, Wo);
    qkv_kernel<<<dim3(NROWS / 128, TD / 128, 3), 256, GEMM_SMEM>>>();
    attn_kernel<<<dim3(NSEQ / 128, NBH), 256>>>();
    out_kernel<<<dim3(NROWS / 128, TD / 128), 256, GEMM_SMEM>>>(bo, x, out);
}

// round 9
// speedup vs baseline: 9.0803x; 1.1259x over previous
#include <cuda_runtime.h>
#include <cuda_bf16.h>
#include <cstdint>

#define TD 768
#define NHEADS 12
#define HDIM 64
#define NSEQ 2048
#define NROWS 4096
#define NBH 24
#define ATT_SCALE 0.125f
#define LN_EPS 1e-5f
#define LOG2E 1.4426950408889634f

typedef __nv_bfloat16 bf16;

__device__ bf16 g_h[(size_t)NROWS * TD];
__device__ bf16 g_wt[4][(size_t)TD * TD];            // W^T [n][k]
__device__ bf16 g_q[(size_t)NBH * NSEQ * HDIM];      // pre-scaled by log2(e)
__device__ bf16 g_k[(size_t)NBH * NSEQ * HDIM];
__device__ bf16 g_vt[(size_t)NBH * HDIM * NSEQ];     // V^T [bh][d][seq]
__device__ bf16 g_vals[(size_t)NROWS * TD];

// ---------------- helpers ----------------
__device__ __forceinline__ uint32_t smem_u32(const void* p) {
    uint32_t a;
    asm("{ .reg .u64 t; cvta.to.shared.u64 t, %1; cvt.u32.u64 %0, t; }" : "=r"(a) : "l"(p));
    return a;
}
__device__ __forceinline__ uint32_t row128(int r, int cb) {
    uint32_t o = (uint32_t)(r * 128 + cb);
    return o ^ ((o >> 3) & 0x70);
}
// pack two floats to bf16x2 in ONE instruction (low = a, high = b)
__device__ __forceinline__ uint32_t pk2(float a, float b) {
    uint32_t r;
    asm("cvt.rn.satfinite.bf16x2.f32 %0, %1, %2;" : "=r"(r) : "f"(b), "f"(a));
    return r;
}
// single-MUFU exp2
__device__ __forceinline__ float ex2(float x) {
    float r;
    asm("ex2.approx.ftz.f32 %0, %1;" : "=f"(r) : "f"(x));
    return r;
}
__device__ __forceinline__ void ldsm4(uint32_t& r0, uint32_t& r1, uint32_t& r2, uint32_t& r3,
                                      uint32_t addr) {
    asm volatile("ldmatrix.sync.aligned.m8n8.x4.shared.b16 {%0,%1,%2,%3}, [%4];"
        : "=r"(r0), "=r"(r1), "=r"(r2), "=r"(r3) : "r"(addr));
}
__device__ __forceinline__ void mma16816(float* c, const uint32_t* a, const uint32_t* b) {
    asm volatile("mma.sync.aligned.m16n8k16.row.col.f32.bf16.bf16.f32 "
        "{%0,%1,%2,%3}, {%4,%5,%6,%7}, {%8,%9}, {%0,%1,%2,%3};"
        : "+f"(c[0]), "+f"(c[1]), "+f"(c[2]), "+f"(c[3])
        : "r"(a[0]), "r"(a[1]), "r"(a[2]), "r"(a[3]), "r"(b[0]), "r"(b[1]));
}
#define CP16(dst, src) asm volatile("cp.async.cg.shared.global [%0], [%1], 16;" :: "r"(dst), "l"(src))
#define CP_COMMIT()    asm volatile("cp.async.commit_group;")
#define CP_WAIT0()     asm volatile("cp.async.wait_group 0;")
#define CP_WAIT1()     asm volatile("cp.async.wait_group 1;")

// ---------------- LayerNorm -> bf16 ----------------
__global__ __launch_bounds__(256) void ln_kernel(const float* __restrict__ x,
                                                 const float* __restrict__ gamma,
                                                 const float* __restrict__ beta) {
    int row = blockIdx.x;
    const float* xr = x + (size_t)row * TD;
    float v[3], sum = 0.f, sq = 0.f;
#pragma unroll
    for (int p = 0; p < 3; p++) {
        v[p] = xr[threadIdx.x + p * 256];
        sum += v[p]; sq += v[p] * v[p];
    }
#pragma unroll
    for (int o = 16; o; o >>= 1) {
        sum += __shfl_xor_sync(~0u, sum, o);
        sq  += __shfl_xor_sync(~0u, sq, o);
    }
    __shared__ float ss[8], sv[8];
    int w = threadIdx.x >> 5, l = threadIdx.x & 31;
    if (l == 0) { ss[w] = sum; sv[w] = sq; }
    __syncthreads();
    if (w == 0) {
        sum = ss[l & 7]; sq = sv[l & 7];
#pragma unroll
        for (int o = 4; o; o >>= 1) {
            sum += __shfl_xor_sync(~0u, sum, o);
            sq  += __shfl_xor_sync(~0u, sq, o);
        }
        if (l == 0) { ss[0] = sum; sv[0] = sq; }
    }
    __syncthreads();
    float mean = ss[0] * (1.f / TD);
    float rstd = rsqrtf(sv[0] * (1.f / TD) - mean * mean + LN_EPS);
#pragma unroll
    for (int p = 0; p < 3; p++) {
        int i = threadIdx.x + p * 256;
        g_h[(size_t)row * TD + i] =
            __float2bfloat16_rn((v[p] - mean) * rstd * gamma[i] + beta[i]);
    }
}

// ---------------- Weight transpose: wt[n][k] = W[k][n] (bf16) ----------------
__global__ __launch_bounds__(256) void wtrans_kernel(const float* __restrict__ Wq,
                                                     const float* __restrict__ Wk,
                                                     const float* __restrict__ Wv,
                                                     const float* __restrict__ Wo) {
    int z = blockIdx.z;
    const float* W = (z == 0) ? Wq : (z == 1) ? Wk : (z == 2) ? Wv : Wo;
    __shared__ float t[32][33];
    int n0 = blockIdx.x * 32, k0 = blockIdx.y * 32;
    int tx = threadIdx.x, ty = threadIdx.y;
#pragma unroll
    for (int i = 0; i < 4; i++)
        t[ty + 8 * i][tx] = W[(size_t)(k0 + ty + 8 * i) * TD + n0 + tx];
    __syncthreads();
#pragma unroll
    for (int i = 0; i < 4; i++)
        g_wt[z][(size_t)(n0 + ty + 8 * i) * TD + k0 + tx] =
            __float2bfloat16_rn(t[tx][ty + 8 * i]);
}

// ---------------- core 128x128 GEMM mainloop (cp.async double-buffered) -----
__device__ __forceinline__ void gemm128(const bf16* __restrict__ A, const bf16* __restrict__ Bt,
                                        char* smem, float c[4][4][4], int m0, int n0) {
    int tid = threadIdx.x, warp = tid >> 5, lane = tid & 31;
    int wm = (warp >> 2) * 64, wn = (warp & 3) * 32;
    uint32_t sb = smem_u32(smem);
    int arow = wm + (lane & 15);
    int acolx = (lane & 16) ? 16 : 0;
    int brow0 = wn + ((lane & 16) ? 8 : 0) + (lane & 7);
    int bcolx = (lane & 8) ? 16 : 0;

    int lr = tid >> 3, lch = tid & 7;
    uint32_t lsw[4];
#pragma unroll
    for (int p = 0; p < 4; p++) lsw[p] = row128(lr + p * 32, lch * 16);

#pragma unroll
    for (int p = 0; p < 4; p++) {
        int r = lr + p * 32;
        CP16(sb + lsw[p],         A  + (size_t)(m0 + r) * TD + lch * 8);
        CP16(sb + 16384 + lsw[p], Bt + (size_t)(n0 + r) * TD + lch * 8);
    }
    CP_COMMIT();

    for (int i = 0; i < 12; i++) {
        uint32_t stg = (uint32_t)(i & 1) * 32768;
        if (i < 11) {
            uint32_t nst = (uint32_t)((i + 1) & 1) * 32768;
#pragma unroll
            for (int p = 0; p < 4; p++) {
                int r = lr + p * 32;
                CP16(sb + nst + lsw[p],         A  + (size_t)(m0 + r) * TD + (i + 1) * 64 + lch * 8);
                CP16(sb + nst + 16384 + lsw[p], Bt + (size_t)(n0 + r) * TD + (i + 1) * 64 + lch * 8);
            }
            CP_COMMIT();
            CP_WAIT1();
        } else {
            CP_WAIT0();
        }
        __syncthreads();
#pragma unroll
        for (int ks = 0; ks < 4; ks++) {
            uint32_t af[4][4], bfr[4][2];
#pragma unroll
            for (int mf = 0; mf < 4; mf++)
                ldsm4(af[mf][0], af[mf][1], af[mf][2], af[mf][3],
                      sb + stg + row128(arow + mf * 16, ks * 32 + acolx));
#pragma unroll
            for (int j = 0; j < 4; j += 2)
                ldsm4(bfr[j][0], bfr[j][1], bfr[j + 1][0], bfr[j + 1][1],
                      sb + stg + 16384 + row128(brow0 + j * 8, ks * 32 + bcolx));
#pragma unroll
            for (int mf = 0; mf < 4; mf++)
#pragma unroll
                for (int nf = 0; nf < 4; nf++)
                    mma16816(c[mf][nf], af[mf], bfr[nf]);
        }
        __syncthreads();
    }
}

// ---------------- QKV GEMM (Q scaled by log2e; V written transposed) --------
#define GEMM_SMEM 65536
__global__ __launch_bounds__(256) void qkv_kernel() {
    extern __shared__ char smem[];
    int z = blockIdx.z;
    int m0 = blockIdx.x * 128, n0 = blockIdx.y * 128;
    float c[4][4][4] = {};
    gemm128(g_h, g_wt[z], smem, c, m0, n0);

    int tid = threadIdx.x, warp = tid >> 5, lane = tid & 31;
    int wm = (warp >> 2) * 64, wn = (warp & 3) * 32;

    if (z < 2) {
        bf16* G = (z == 0) ? g_q : g_k;
        float sc = (z == 0) ? LOG2E : 1.0f;   // fold exp->exp2 scaling into Q
#pragma unroll
        for (int mf = 0; mf < 4; mf++) {
            int row = m0 + wm + mf * 16 + (lane >> 2);
            int batch = row >> 11, seq = row & (NSEQ - 1);
#pragma unroll
            for (int nf = 0; nf < 4; nf++) {
                int col = n0 + wn + nf * 8 + 2 * (lane & 3);
                int head = col >> 6, d = col & 63;
                bf16* D = G + ((size_t)(batch * NHEADS + head) * NSEQ + seq) * HDIM + d;
                *(uint32_t*)D = pk2(c[mf][nf][0] * sc, c[mf][nf][1] * sc);
                *(uint32_t*)(D + 8 * HDIM) = pk2(c[mf][nf][2] * sc, c[mf][nf][3] * sc);
            }
        }
    } else {
        // V: transpose in smem, write g_vt[bh][d][seq] directly
        bf16* ts = (bf16*)smem;     // [128 cols n][136 pitch m]
        __syncthreads();            // gemm128 left smem free
#pragma unroll
        for (int mf = 0; mf < 4; mf++) {
            int lr0 = wm + mf * 16 + (lane >> 2);
#pragma unroll
            for (int nf = 0; nf < 4; nf++) {
                int lc = wn + nf * 8 + 2 * (lane & 3);
                uint32_t lo = pk2(c[mf][nf][0], c[mf][nf][2]);
                uint32_t hi = pk2(c[mf][nf][1], c[mf][nf][3]);
                ts[(size_t)lc * 136 + lr0]           = __ushort_as_bfloat16((unsigned short)(lo & 0xffff));
                ts[(size_t)lc * 136 + lr0 + 8]       = __ushort_as_bfloat16((unsigned short)(lo >> 16));
                ts[(size_t)(lc + 1) * 136 + lr0]     = __ushort_as_bfloat16((unsigned short)(hi & 0xffff));
                ts[(size_t)(lc + 1) * 136 + lr0 + 8] = __ushort_as_bfloat16((unsigned short)(hi >> 16));
            }
        }
        __syncthreads();
        int n = tid >> 1, mh = (tid & 1) * 64;
        int col = n0 + n, head = col >> 6, d = col & 63;
        int batch = blockIdx.x >> 4;
        int seq0 = (m0 & (NSEQ - 1)) + mh;
        bf16* D = g_vt + ((size_t)(batch * NHEADS + head) * HDIM + d) * NSEQ + seq0;
#pragma unroll
        for (int s = 0; s < 8; s++)
            *(uint4*)(D + s * 8) = *(uint4*)&ts[(size_t)n * 136 + mh + s * 8];
    }
}

// ---------------- Attention: FA2-style, 8 warps x 16 q rows, 2 CTA/SM -------
// smem: Q 16K @0 | K 2x8K @16384 | V^T 2x8K @32768  (48KB static)
__global__ __launch_bounds__(256, 2) void attn_kernel() {
    __shared__ char smem[49152];
    int tid = threadIdx.x, warp = tid >> 5, lane = tid & 31;
    int q0 = blockIdx.x * 128, bh = blockIdx.y;

    const bf16* Qg = g_q + (size_t)bh * NSEQ * HDIM;
    const bf16* Kg = g_k + (size_t)bh * NSEQ * HDIM;
    const bf16* Vt = g_vt + (size_t)bh * HDIM * NSEQ;
    uint32_t sb = smem_u32(smem);

#pragma unroll
    for (int p = 0; p < 4; p++) {
        int idx = tid + p * 256;
        int r = idx >> 3, ch = idx & 7;
        CP16(sb + row128(r, ch * 16), Qg + (size_t)(q0 + r) * HDIM + ch * 8);
    }
    CP_COMMIT();

    int kr = tid >> 3, kch = tid & 7;
    uint32_t ksw[2];
    ksw[0] = row128(kr, kch * 16);
    ksw[1] = row128(kr + 32, kch * 16);
#pragma unroll
    for (int p = 0; p < 2; p++) {
        int r = kr + p * 32;
        CP16(sb + 16384 + ksw[p], Kg + (size_t)r * HDIM + kch * 8);
        CP16(sb + 32768 + ksw[p], Vt + (size_t)r * NSEQ + kch * 8);
    }
    CP_COMMIT();

    CP_WAIT1();
    __syncthreads();

    uint32_t qf[4][4];
    int arow = warp * 16 + (lane & 15);
    int acolx = (lane & 16) ? 16 : 0;
#pragma unroll
    for (int ks = 0; ks < 4; ks++)
        ldsm4(qf[ks][0], qf[ks][1], qf[ks][2], qf[ks][3],
              sb + row128(arow, ks * 32 + acolx));

    float of[8][4] = {};
    float lsum[2] = {};
    int brow0 = ((lane & 16) ? 8 : 0) + (lane & 7);
    int bcolx = (lane & 8) ? 16 : 0;

    for (int kt = 0; kt < NSEQ / 64; kt++) {
        uint32_t stg = (uint32_t)(kt & 1) * 8192;
        if (kt < NSEQ / 64 - 1) {
            uint32_t nst = (uint32_t)((kt + 1) & 1) * 8192;
#pragma unroll
            for (int p = 0; p < 2; p++) {
                int r = kr + p * 32;
                CP16(sb + 16384 + nst + ksw[p], Kg + (size_t)((kt + 1) * 64 + r) * HDIM + kch * 8);
                CP16(sb + 32768 + nst + ksw[p], Vt + (size_t)r * NSEQ + (kt + 1) * 64 + kch * 8);
            }
            CP_COMMIT();
            CP_WAIT1();
        } else {
            CP_WAIT0();
        }
        __syncthreads();

        // S' = (log2e*Q) @ K^T in two 32-kv halves; P = exp2(S')
        uint32_t pf[4][4];
#pragma unroll
        for (int half = 0; half < 2; half++) {
            float sf[4][4] = {};
#pragma unroll
            for (int ks = 0; ks < 4; ks++) {
                uint32_t bfr[4][2];
#pragma unroll
                for (int j = 0; j < 4; j += 2)
                    ldsm4(bfr[j][0], bfr[j][1], bfr[j + 1][0], bfr[j + 1][1],
                          sb + 16384 + stg + row128(brow0 + half * 32 + j * 8, ks * 32 + bcolx));
#pragma unroll
                for (int nf = 0; nf < 4; nf++)
                    mma16816(sf[nf], qf[ks], bfr[nf]);
            }
#pragma unroll
            for (int j = 0; j < 2; j++) {
                float e00 = ex2(sf[2 * j][0]),     e01 = ex2(sf[2 * j][1]);
                float e02 = ex2(sf[2 * j][2]),     e03 = ex2(sf[2 * j][3]);
                float e10 = ex2(sf[2 * j + 1][0]), e11 = ex2(sf[2 * j + 1][1]);
                float e12 = ex2(sf[2 * j + 1][2]), e13 = ex2(sf[2 * j + 1][3]);
                int pj = half * 2 + j;
                pf[pj][0] = pk2(e00, e01);
                pf[pj][1] = pk2(e02, e03);
                pf[pj][2] = pk2(e10, e11);
                pf[pj][3] = pk2(e12, e13);
                lsum[0] += e00 + e01 + e10 + e11;
                lsum[1] += e02 + e03 + e12 + e13;
            }
        }

        // O += P @ V : B from V^T [d][kv]
#pragma unroll
        for (int ks = 0; ks < 4; ks++) {
            uint32_t bfr[8][2];
#pragma unroll
            for (int j = 0; j < 8; j += 2)
                ldsm4(bfr[j][0], bfr[j][1], bfr[j + 1][0], bfr[j + 1][1],
                      sb + 32768 + stg + row128(brow0 + j * 8, ks * 32 + bcolx));
#pragma unroll
            for (int nf = 0; nf < 8; nf++)
                mma16816(of[nf], pf[ks], bfr[nf]);
        }
        __syncthreads();
    }

    float scale[2];
#pragma unroll
    for (int h = 0; h < 2; h++) {
        float l = lsum[h];
        l += __shfl_xor_sync(~0u, l, 1);
        l += __shfl_xor_sync(~0u, l, 2);
        scale[h] = ATT_SCALE / l;
    }
    int batch = bh / NHEADS, head = bh % NHEADS;
    int r0 = q0 + warp * 16 + (lane >> 2);
#pragma unroll
    for (int nf = 0; nf < 8; nf++) {
        int d = nf * 8 + 2 * (lane & 3);
        bf16* D = g_vals + ((size_t)(batch * NSEQ + r0)) * TD + head * HDIM + d;
        *(uint32_t*)D = pk2(of[nf][0] * scale[0], of[nf][1] * scale[0]);
        *(uint32_t*)(D + (size_t)8 * TD) = pk2(of[nf][2] * scale[1], of[nf][3] * scale[1]);
    }
}

// ---------------- Output projection: out = vals @ Wo + bo + x ----------------
__global__ __launch_bounds__(256) void out_kernel(const float* __restrict__ bo,
                                                  const float* __restrict__ x,
                                                  float* __restrict__ out) {
    extern __shared__ char smem[];
    int m0 = blockIdx.x * 128, n0 = blockIdx.y * 128;
    float c[4][4][4] = {};
    gemm128(g_vals, g_wt[3], smem, c, m0, n0);

    int tid = threadIdx.x, warp = tid >> 5, lane = tid & 31;
    int wm = (warp >> 2) * 64, wn = (warp & 3) * 32;
#pragma unroll
    for (int mf = 0; mf < 4; mf++) {
        int row = m0 + wm + mf * 16 + (lane >> 2);
#pragma unroll
        for (int nf = 0; nf < 4; nf++) {
            int col = n0 + wn + nf * 8 + 2 * (lane & 3);
            float2 bv = *(const float2*)(bo + col);
            size_t off0 = (size_t)row * TD + col;
            size_t off1 = (size_t)(row + 8) * TD + col;
            float2 x0 = *(const float2*)(x + off0);
            float2 x1 = *(const float2*)(x + off1);
            *(float2*)(out + off0) = make_float2(c[mf][nf][0] + bv.x + x0.x,
                                                 c[mf][nf][1] + bv.y + x0.y);
            *(float2*)(out + off1) = make_float2(c[mf][nf][2] + bv.x + x1.x,
                                                 c[mf][nf][3] + bv.y + x1.y);
        }
    }
}

// ---------------------------------------------------------------------------
extern "C" void kernel_launch(void* const* d_in, const int* in_sizes, int n_in,
                              void* d_out, int out_size) {
    (void)in_sizes; (void)n_in; (void)out_size;
    const float* x     = (const float*)d_in[0];
    const float* Wq    = (const float*)d_in[1];
    const float* Wk    = (const float*)d_in[2];
    const float* Wv    = (const float*)d_in[3];
    const float* Wo    = (const float*)d_in[4];
    const float* bo    = (const float*)d_in[5];
    const float* gamma = (const float*)d_in[6];
    const float* beta  = (const float*)d_in[7];
    float* out = (float*)d_out;

    cudaFuncSetAttribute(qkv_kernel, cudaFuncAttributeMaxDynamicSharedMemorySize, GEMM_SMEM);
    cudaFuncSetAttribute(out_kernel, cudaFuncAttributeMaxDynamicSharedMemorySize, GEMM_SMEM);

    ln_kernel<<<NROWS, 256>>>(x, gamma, beta);
    wtrans_kernel<<<dim3(TD / 32, TD / 32, 4), dim3(32, 8)>>>(Wq, Wk, Wv, Wo);
    qkv_kernel<<<dim3(NROWS / 128, TD / 128, 3), 256, GEMM_SMEM>>>();
    attn_kernel<<<dim3(NSEQ / 128, NBH), 256>>>();
    out_kernel<<<dim3(NROWS / 128, TD / 128), 256, GEMM_SMEM>>>(bo, x, out);
}

// round 10
// speedup vs baseline: 9.1754x; 1.0105x over previous
#include <cuda_runtime.h>
#include <cuda_bf16.h>
#include <cstdint>

#define TD 768
#define NHEADS 12
#define HDIM 64
#define NSEQ 2048
#define NROWS 4096
#define NBH 24
#define ATT_SCALE 0.125f
#define LN_EPS 1e-5f
#define LOG2E 1.4426950408889634f

typedef __nv_bfloat16 bf16;

__device__ bf16 g_h[(size_t)NROWS * TD];
__device__ bf16 g_wt[4][(size_t)TD * TD];            // W^T [n][k]
__device__ bf16 g_q[(size_t)NBH * NSEQ * HDIM];      // pre-scaled by log2(e)
__device__ bf16 g_k[(size_t)NBH * NSEQ * HDIM];
__device__ bf16 g_vt[(size_t)NBH * HDIM * NSEQ];     // V^T [bh][d][seq]
__device__ bf16 g_vals[(size_t)NROWS * TD];

// ---------------- helpers ----------------
__device__ __forceinline__ uint32_t smem_u32(const void* p) {
    uint32_t a;
    asm("{ .reg .u64 t; cvta.to.shared.u64 t, %1; cvt.u32.u64 %0, t; }" : "=r"(a) : "l"(p));
    return a;
}
__device__ __forceinline__ uint32_t row128(int r, int cb) {
    uint32_t o = (uint32_t)(r * 128 + cb);
    return o ^ ((o >> 3) & 0x70);
}
// pack two floats to bf16x2 in ONE instruction (low = a, high = b)
__device__ __forceinline__ uint32_t pk2(float a, float b) {
    uint32_t r;
    asm("cvt.rn.satfinite.bf16x2.f32 %0, %1, %2;" : "=r"(r) : "f"(b), "f"(a));
    return r;
}
// single-MUFU exp2
__device__ __forceinline__ float ex2(float x) {
    float r;
    asm("ex2.approx.ftz.f32 %0, %1;" : "=f"(r) : "f"(x));
    return r;
}
__device__ __forceinline__ void ldsm4(uint32_t& r0, uint32_t& r1, uint32_t& r2, uint32_t& r3,
                                      uint32_t addr) {
    asm volatile("ldmatrix.sync.aligned.m8n8.x4.shared.b16 {%0,%1,%2,%3}, [%4];"
        : "=r"(r0), "=r"(r1), "=r"(r2), "=r"(r3) : "r"(addr));
}
__device__ __forceinline__ void mma16816(float* c, const uint32_t* a, const uint32_t* b) {
    asm volatile("mma.sync.aligned.m16n8k16.row.col.f32.bf16.bf16.f32 "
        "{%0,%1,%2,%3}, {%4,%5,%6,%7}, {%8,%9}, {%0,%1,%2,%3};"
        : "+f"(c[0]), "+f"(c[1]), "+f"(c[2]), "+f"(c[3])
        : "r"(a[0]), "r"(a[1]), "r"(a[2]), "r"(a[3]), "r"(b[0]), "r"(b[1]));
}
#define CP16(dst, src) asm volatile("cp.async.cg.shared.global [%0], [%1], 16;" :: "r"(dst), "l"(src))
#define CP_COMMIT()    asm volatile("cp.async.commit_group;")
#define CP_WAIT0()     asm volatile("cp.async.wait_group 0;")
#define CP_WAIT1()     asm volatile("cp.async.wait_group 1;")

// ---------------- LayerNorm -> bf16 ----------------
__global__ __launch_bounds__(256) void ln_kernel(const float* __restrict__ x,
                                                 const float* __restrict__ gamma,
                                                 const float* __restrict__ beta) {
    int row = blockIdx.x;
    const float* xr = x + (size_t)row * TD;
    float v[3], sum = 0.f, sq = 0.f;
#pragma unroll
    for (int p = 0; p < 3; p++) {
        v[p] = xr[threadIdx.x + p * 256];
        sum += v[p]; sq += v[p] * v[p];
    }
#pragma unroll
    for (int o = 16; o; o >>= 1) {
        sum += __shfl_xor_sync(~0u, sum, o);
        sq  += __shfl_xor_sync(~0u, sq, o);
    }
    __shared__ float ss[8], sv[8];
    int w = threadIdx.x >> 5, l = threadIdx.x & 31;
    if (l == 0) { ss[w] = sum; sv[w] = sq; }
    __syncthreads();
    if (w == 0) {
        sum = ss[l & 7]; sq = sv[l & 7];
#pragma unroll
        for (int o = 4; o; o >>= 1) {
            sum += __shfl_xor_sync(~0u, sum, o);
            sq  += __shfl_xor_sync(~0u, sq, o);
        }
        if (l == 0) { ss[0] = sum; sv[0] = sq; }
    }
    __syncthreads();
    float mean = ss[0] * (1.f / TD);
    float rstd = rsqrtf(sv[0] * (1.f / TD) - mean * mean + LN_EPS);
#pragma unroll
    for (int p = 0; p < 3; p++) {
        int i = threadIdx.x + p * 256;
        g_h[(size_t)row * TD + i] =
            __float2bfloat16_rn((v[p] - mean) * rstd * gamma[i] + beta[i]);
    }
}

// ---------------- Weight transpose: wt[n][k] = W[k][n] (bf16) ----------------
__global__ __launch_bounds__(256) void wtrans_kernel(const float* __restrict__ Wq,
                                                     const float* __restrict__ Wk,
                                                     const float* __restrict__ Wv,
                                                     const float* __restrict__ Wo) {
    int z = blockIdx.z;
    const float* W = (z == 0) ? Wq : (z == 1) ? Wk : (z == 2) ? Wv : Wo;
    __shared__ float t[32][33];
    int n0 = blockIdx.x * 32, k0 = blockIdx.y * 32;
    int tx = threadIdx.x, ty = threadIdx.y;
#pragma unroll
    for (int i = 0; i < 4; i++)
        t[ty + 8 * i][tx] = W[(size_t)(k0 + ty + 8 * i) * TD + n0 + tx];
    __syncthreads();
#pragma unroll
    for (int i = 0; i < 4; i++)
        g_wt[z][(size_t)(n0 + ty + 8 * i) * TD + k0 + tx] =
            __float2bfloat16_rn(t[tx][ty + 8 * i]);
}

// ---------------- core 128x128 GEMM mainloop (cp.async double-buffered) -----
__device__ __forceinline__ void gemm128(const bf16* __restrict__ A, const bf16* __restrict__ Bt,
                                        char* smem, float c[4][4][4], int m0, int n0) {
    int tid = threadIdx.x, warp = tid >> 5, lane = tid & 31;
    int wm = (warp >> 2) * 64, wn = (warp & 3) * 32;
    uint32_t sb = smem_u32(smem);
    int arow = wm + (lane & 15);
    int acolx = (lane & 16) ? 16 : 0;
    int brow0 = wn + ((lane & 16) ? 8 : 0) + (lane & 7);
    int bcolx = (lane & 8) ? 16 : 0;

    int lr = tid >> 3, lch = tid & 7;
    uint32_t lsw[4];
#pragma unroll
    for (int p = 0; p < 4; p++) lsw[p] = row128(lr + p * 32, lch * 16);

#pragma unroll
    for (int p = 0; p < 4; p++) {
        int r = lr + p * 32;
        CP16(sb + lsw[p],         A  + (size_t)(m0 + r) * TD + lch * 8);
        CP16(sb + 16384 + lsw[p], Bt + (size_t)(n0 + r) * TD + lch * 8);
    }
    CP_COMMIT();

    for (int i = 0; i < 12; i++) {
        uint32_t stg = (uint32_t)(i & 1) * 32768;
        if (i < 11) {
            uint32_t nst = (uint32_t)((i + 1) & 1) * 32768;
#pragma unroll
            for (int p = 0; p < 4; p++) {
                int r = lr + p * 32;
                CP16(sb + nst + lsw[p],         A  + (size_t)(m0 + r) * TD + (i + 1) * 64 + lch * 8);
                CP16(sb + nst + 16384 + lsw[p], Bt + (size_t)(n0 + r) * TD + (i + 1) * 64 + lch * 8);
            }
            CP_COMMIT();
            CP_WAIT1();
        } else {
            CP_WAIT0();
        }
        __syncthreads();
#pragma unroll
        for (int ks = 0; ks < 4; ks++) {
            uint32_t af[4][4], bfr[4][2];
#pragma unroll
            for (int mf = 0; mf < 4; mf++)
                ldsm4(af[mf][0], af[mf][1], af[mf][2], af[mf][3],
                      sb + stg + row128(arow + mf * 16, ks * 32 + acolx));
#pragma unroll
            for (int j = 0; j < 4; j += 2)
                ldsm4(bfr[j][0], bfr[j][1], bfr[j + 1][0], bfr[j + 1][1],
                      sb + stg + 16384 + row128(brow0 + j * 8, ks * 32 + bcolx));
#pragma unroll
            for (int mf = 0; mf < 4; mf++)
#pragma unroll
                for (int nf = 0; nf < 4; nf++)
                    mma16816(c[mf][nf], af[mf], bfr[nf]);
        }
        __syncthreads();
    }
}

// ---------------- QKV GEMM (Q scaled by log2e; V written transposed) --------
#define GEMM_SMEM 65536
__global__ __launch_bounds__(256) void qkv_kernel() {
    extern __shared__ char smem[];
    int z = blockIdx.z;
    int m0 = blockIdx.x * 128, n0 = blockIdx.y * 128;
    float c[4][4][4] = {};
    gemm128(g_h, g_wt[z], smem, c, m0, n0);

    int tid = threadIdx.x, warp = tid >> 5, lane = tid & 31;
    int wm = (warp >> 2) * 64, wn = (warp & 3) * 32;

    if (z < 2) {
        bf16* G = (z == 0) ? g_q : g_k;
        float sc = (z == 0) ? LOG2E : 1.0f;   // fold exp->exp2 scaling into Q
#pragma unroll
        for (int mf = 0; mf < 4; mf++) {
            int row = m0 + wm + mf * 16 + (lane >> 2);
            int batch = row >> 11, seq = row & (NSEQ - 1);
#pragma unroll
            for (int nf = 0; nf < 4; nf++) {
                int col = n0 + wn + nf * 8 + 2 * (lane & 3);
                int head = col >> 6, d = col & 63;
                bf16* D = G + ((size_t)(batch * NHEADS + head) * NSEQ + seq) * HDIM + d;
                *(uint32_t*)D = pk2(c[mf][nf][0] * sc, c[mf][nf][1] * sc);
                *(uint32_t*)(D + 8 * HDIM) = pk2(c[mf][nf][2] * sc, c[mf][nf][3] * sc);
            }
        }
    } else {
        // V: transpose in smem, write g_vt[bh][d][seq] directly
        bf16* ts = (bf16*)smem;     // [128 cols n][136 pitch m]
        __syncthreads();            // gemm128 left smem free
#pragma unroll
        for (int mf = 0; mf < 4; mf++) {
            int lr0 = wm + mf * 16 + (lane >> 2);
#pragma unroll
            for (int nf = 0; nf < 4; nf++) {
                int lc = wn + nf * 8 + 2 * (lane & 3);
                uint32_t lo = pk2(c[mf][nf][0], c[mf][nf][2]);
                uint32_t hi = pk2(c[mf][nf][1], c[mf][nf][3]);
                ts[(size_t)lc * 136 + lr0]           = __ushort_as_bfloat16((unsigned short)(lo & 0xffff));
                ts[(size_t)lc * 136 + lr0 + 8]       = __ushort_as_bfloat16((unsigned short)(lo >> 16));
                ts[(size_t)(lc + 1) * 136 + lr0]     = __ushort_as_bfloat16((unsigned short)(hi & 0xffff));
                ts[(size_t)(lc + 1) * 136 + lr0 + 8] = __ushort_as_bfloat16((unsigned short)(hi >> 16));
            }
        }
        __syncthreads();
        int n = tid >> 1, mh = (tid & 1) * 64;
        int col = n0 + n, head = col >> 6, d = col & 63;
        int batch = blockIdx.x >> 4;
        int seq0 = (m0 & (NSEQ - 1)) + mh;
        bf16* D = g_vt + ((size_t)(batch * NHEADS + head) * HDIM + d) * NSEQ + seq0;
#pragma unroll
        for (int s = 0; s < 8; s++)
            *(uint4*)(D + s * 8) = *(uint4*)&ts[(size_t)n * 136 + mh + s * 8];
    }
}

// ---------------- Attention: 64 q rows/CTA, 4 warps, 4 CTA/SM ---------------
// smem: Q 8K @0 | K 2x8K @8192 | V^T 2x8K @24576  (40KB static)
__global__ __launch_bounds__(128, 4) void attn_kernel() {
    __shared__ char smem[40960];
    int tid = threadIdx.x, warp = tid >> 5, lane = tid & 31;
    int q0 = blockIdx.x * 64, bh = blockIdx.y;

    const bf16* Qg = g_q + (size_t)bh * NSEQ * HDIM;
    const bf16* Kg = g_k + (size_t)bh * NSEQ * HDIM;
    const bf16* Vt = g_vt + (size_t)bh * HDIM * NSEQ;
    uint32_t sb = smem_u32(smem);

    // Q tile [64][64] (512 uint4, 4 per thread)
#pragma unroll
    for (int p = 0; p < 4; p++) {
        int idx = tid + p * 128;
        int r = idx >> 3, ch = idx & 7;
        CP16(sb + row128(r, ch * 16), Qg + (size_t)(q0 + r) * HDIM + ch * 8);
    }
    CP_COMMIT();

    // K/V tile kt=0 into buf 0 (4 uint4 each per thread)
#pragma unroll
    for (int p = 0; p < 4; p++) {
        int idx = tid + p * 128;
        int r = idx >> 3, ch = idx & 7;
        uint32_t sw = row128(r, ch * 16);
        CP16(sb + 8192 + sw,  Kg + (size_t)r * HDIM + ch * 8);
        CP16(sb + 24576 + sw, Vt + (size_t)r * NSEQ + ch * 8);
    }
    CP_COMMIT();

    CP_WAIT1();
    __syncthreads();

    uint32_t qf[4][4];
    int arow = warp * 16 + (lane & 15);
    int acolx = (lane & 16) ? 16 : 0;
#pragma unroll
    for (int ks = 0; ks < 4; ks++)
        ldsm4(qf[ks][0], qf[ks][1], qf[ks][2], qf[ks][3],
              sb + row128(arow, ks * 32 + acolx));

    float of[8][4] = {};
    float lsum[2] = {};
    int brow0 = ((lane & 16) ? 8 : 0) + (lane & 7);
    int bcolx = (lane & 8) ? 16 : 0;

    for (int kt = 0; kt < NSEQ / 64; kt++) {
        uint32_t stg = (uint32_t)(kt & 1) * 8192;
        if (kt < NSEQ / 64 - 1) {
            uint32_t nst = (uint32_t)((kt + 1) & 1) * 8192;
#pragma unroll
            for (int p = 0; p < 4; p++) {
                int idx = tid + p * 128;
                int r = idx >> 3, ch = idx & 7;
                uint32_t sw = row128(r, ch * 16);
                CP16(sb + 8192 + nst + sw,  Kg + (size_t)((kt + 1) * 64 + r) * HDIM + ch * 8);
                CP16(sb + 24576 + nst + sw, Vt + (size_t)r * NSEQ + (kt + 1) * 64 + ch * 8);
            }
            CP_COMMIT();
            CP_WAIT1();
        } else {
            CP_WAIT0();
        }
        __syncthreads();

        // S' = (log2e*Q) @ K^T in two 32-kv halves; P = exp2(S')
        uint32_t pf[4][4];
#pragma unroll
        for (int half = 0; half < 2; half++) {
            float sf[4][4] = {};
#pragma unroll
            for (int ks = 0; ks < 4; ks++) {
                uint32_t bfr[4][2];
#pragma unroll
                for (int j = 0; j < 4; j += 2)
                    ldsm4(bfr[j][0], bfr[j][1], bfr[j + 1][0], bfr[j + 1][1],
                          sb + 8192 + stg + row128(brow0 + half * 32 + j * 8, ks * 32 + bcolx));
#pragma unroll
                for (int nf = 0; nf < 4; nf++)
                    mma16816(sf[nf], qf[ks], bfr[nf]);
            }
#pragma unroll
            for (int j = 0; j < 2; j++) {
                float e00 = ex2(sf[2 * j][0]),     e01 = ex2(sf[2 * j][1]);
                float e02 = ex2(sf[2 * j][2]),     e03 = ex2(sf[2 * j][3]);
                float e10 = ex2(sf[2 * j + 1][0]), e11 = ex2(sf[2 * j + 1][1]);
                float e12 = ex2(sf[2 * j + 1][2]), e13 = ex2(sf[2 * j + 1][3]);
                int pj = half * 2 + j;
                pf[pj][0] = pk2(e00, e01);
                pf[pj][1] = pk2(e02, e03);
                pf[pj][2] = pk2(e10, e11);
                pf[pj][3] = pk2(e12, e13);
                lsum[0] += e00 + e01 + e10 + e11;
                lsum[1] += e02 + e03 + e12 + e13;
            }
        }

        // O += P @ V : B from V^T [d][kv]
#pragma unroll
        for (int ks = 0; ks < 4; ks++) {
            uint32_t bfr[8][2];
#pragma unroll
            for (int j = 0; j < 8; j += 2)
                ldsm4(bfr[j][0], bfr[j][1], bfr[j + 1][0], bfr[j + 1][1],
                      sb + 24576 + stg + row128(brow0 + j * 8, ks * 32 + bcolx));
#pragma unroll
            for (int nf = 0; nf < 8; nf++)
                mma16816(of[nf], pf[ks], bfr[nf]);
        }
        __syncthreads();
    }

    float scale[2];
#pragma unroll
    for (int h = 0; h < 2; h++) {
        float l = lsum[h];
        l += __shfl_xor_sync(~0u, l, 1);
        l += __shfl_xor_sync(~0u, l, 2);
        scale[h] = ATT_SCALE / l;
    }
    int batch = bh / NHEADS, head = bh % NHEADS;
    int r0 = q0 + warp * 16 + (lane >> 2);
#pragma unroll
    for (int nf = 0; nf < 8; nf++) {
        int d = nf * 8 + 2 * (lane & 3);
        bf16* D = g_vals + ((size_t)(batch * NSEQ + r0)) * TD + head * HDIM + d;
        *(uint32_t*)D = pk2(of[nf][0] * scale[0], of[nf][1] * scale[0]);
        *(uint32_t*)(D + (size_t)8 * TD) = pk2(of[nf][2] * scale[1], of[nf][3] * scale[1]);
    }
}

// ---------------- Output projection: out = vals @ Wo + bo + x ----------------
__global__ __launch_bounds__(256) void out_kernel(const float* __restrict__ bo,
                                                  const float* __restrict__ x,
                                                  float* __restrict__ out) {
    extern __shared__ char smem[];
    int m0 = blockIdx.x * 128, n0 = blockIdx.y * 128;
    float c[4][4][4] = {};
    gemm128(g_vals, g_wt[3], smem, c, m0, n0);

    int tid = threadIdx.x, warp = tid >> 5, lane = tid & 31;
    int wm = (warp >> 2) * 64, wn = (warp & 3) * 32;
#pragma unroll
    for (int mf = 0; mf < 4; mf++) {
        int row = m0 + wm + mf * 16 + (lane >> 2);
#pragma unroll
        for (int nf = 0; nf < 4; nf++) {
            int col = n0 + wn + nf * 8 + 2 * (lane & 3);
            float2 bv = *(const float2*)(bo + col);
            size_t off0 = (size_t)row * TD + col;
            size_t off1 = (size_t)(row + 8) * TD + col;
            float2 x0 = *(const float2*)(x + off0);
            float2 x1 = *(const float2*)(x + off1);
            *(float2*)(out + off0) = make_float2(c[mf][nf][0] + bv.x + x0.x,
                                                 c[mf][nf][1] + bv.y + x0.y);
            *(float2*)(out + off1) = make_float2(c[mf][nf][2] + bv.x + x1.x,
                                                 c[mf][nf][3] + bv.y + x1.y);
        }
    }
}

// ---------------------------------------------------------------------------
extern "C" void kernel_launch(void* const* d_in, const int* in_sizes, int n_in,
                              void* d_out, int out_size) {
    (void)in_sizes; (void)n_in; (void)out_size;
    const float* x     = (const float*)d_in[0];
    const float* Wq    = (const float*)d_in[1];
    const float* Wk    = (const float*)d_in[2];
    const float* Wv    = (const float*)d_in[3];
    const float* Wo    = (const float*)d_in[4];
    const float* bo    = (const float*)d_in[5];
    const float* gamma = (const float*)d_in[6];
    const float* beta  = (const float*)d_in[7];
    float* out = (float*)d_out;

    cudaFuncSetAttribute(qkv_kernel, cudaFuncAttributeMaxDynamicSharedMemorySize, GEMM_SMEM);
    cudaFuncSetAttribute(out_kernel, cudaFuncAttributeMaxDynamicSharedMemorySize, GEMM_SMEM);

    ln_kernel<<<NROWS, 256>>>(x, gamma, beta);
    wtrans_kernel<<<dim3(TD / 32, TD / 32, 4), dim3(32, 8)>>>(Wq, Wk, Wv, Wo);
    qkv_kernel<<<dim3(NROWS / 128, TD / 128, 3), 256, GEMM_SMEM>>>();
    attn_kernel<<<dim3(NSEQ / 64, NBH), 128>>>();
    out_kernel<<<dim3(NROWS / 128, TD / 128), 256, GEMM_SMEM>>>(bo, x, out);
}

// round 11
// speedup vs baseline: 9.5369x; 1.0394x over previous
#include <cuda_runtime.h>
#include <cuda_bf16.h>
#include <cstdint>

#define TD 768
#define NHEADS 12
#define HDIM 64
#define NSEQ 2048
#define NROWS 4096
#define NBH 24
#define ATT_SCALE 0.125f
#define LN_EPS 1e-5f
#define LOG2E 1.4426950408889634f

typedef __nv_bfloat16 bf16;

__device__ bf16 g_h[(size_t)NROWS * TD];
__device__ bf16 g_wt[4][(size_t)TD * TD];            // W^T [n][k]
__device__ bf16 g_q[(size_t)NBH * NSEQ * HDIM];      // pre-scaled by log2(e)
__device__ bf16 g_k[(size_t)NBH * NSEQ * HDIM];
__device__ bf16 g_vt[(size_t)NBH * HDIM * NSEQ];     // V^T [bh][d][seq]
__device__ bf16 g_vals[(size_t)NROWS * TD];

// ---------------- helpers ----------------
__device__ __forceinline__ uint32_t smem_u32(const void* p) {
    uint32_t a;
    asm("{ .reg .u64 t; cvta.to.shared.u64 t, %1; cvt.u32.u64 %0, t; }" : "=r"(a) : "l"(p));
    return a;
}
__device__ __forceinline__ uint32_t row128(int r, int cb) {
    uint32_t o = (uint32_t)(r * 128 + cb);
    return o ^ ((o >> 3) & 0x70);
}
// pack two floats to bf16x2 in ONE instruction (low = a, high = b)
__device__ __forceinline__ uint32_t pk2(float a, float b) {
    uint32_t r;
    asm("cvt.rn.satfinite.bf16x2.f32 %0, %1, %2;" : "=r"(r) : "f"(b), "f"(a));
    return r;
}
// single-MUFU exp2
__device__ __forceinline__ float ex2(float x) {
    float r;
    asm("ex2.approx.ftz.f32 %0, %1;" : "=f"(r) : "f"(x));
    return r;
}
__device__ __forceinline__ void ldsm4(uint32_t& r0, uint32_t& r1, uint32_t& r2, uint32_t& r3,
                                      uint32_t addr) {
    asm volatile("ldmatrix.sync.aligned.m8n8.x4.shared.b16 {%0,%1,%2,%3}, [%4];"
        : "=r"(r0), "=r"(r1), "=r"(r2), "=r"(r3) : "r"(addr));
}
__device__ __forceinline__ void mma16816(float* c, const uint32_t* a, const uint32_t* b) {
    asm volatile("mma.sync.aligned.m16n8k16.row.col.f32.bf16.bf16.f32 "
        "{%0,%1,%2,%3}, {%4,%5,%6,%7}, {%8,%9}, {%0,%1,%2,%3};"
        : "+f"(c[0]), "+f"(c[1]), "+f"(c[2]), "+f"(c[3])
        : "r"(a[0]), "r"(a[1]), "r"(a[2]), "r"(a[3]), "r"(b[0]), "r"(b[1]));
}
#define CP16(dst, src) asm volatile("cp.async.cg.shared.global [%0], [%1], 16;" :: "r"(dst), "l"(src))
#define CP_COMMIT()    asm volatile("cp.async.commit_group;")
#define CP_WAIT0()     asm volatile("cp.async.wait_group 0;")
#define CP_WAIT1()     asm volatile("cp.async.wait_group 1;")

// ---------------- LayerNorm -> bf16 ----------------
__global__ __launch_bounds__(256) void ln_kernel(const float* __restrict__ x,
                                                 const float* __restrict__ gamma,
                                                 const float* __restrict__ beta) {
    int row = blockIdx.x;
    const float* xr = x + (size_t)row * TD;
    float v[3], sum = 0.f, sq = 0.f;
#pragma unroll
    for (int p = 0; p < 3; p++) {
        v[p] = xr[threadIdx.x + p * 256];
        sum += v[p]; sq += v[p] * v[p];
    }
#pragma unroll
    for (int o = 16; o; o >>= 1) {
        sum += __shfl_xor_sync(~0u, sum, o);
        sq  += __shfl_xor_sync(~0u, sq, o);
    }
    __shared__ float ss[8], sv[8];
    int w = threadIdx.x >> 5, l = threadIdx.x & 31;
    if (l == 0) { ss[w] = sum; sv[w] = sq; }
    __syncthreads();
    if (w == 0) {
        sum = ss[l & 7]; sq = sv[l & 7];
#pragma unroll
        for (int o = 4; o; o >>= 1) {
            sum += __shfl_xor_sync(~0u, sum, o);
            sq  += __shfl_xor_sync(~0u, sq, o);
        }
        if (l == 0) { ss[0] = sum; sv[0] = sq; }
    }
    __syncthreads();
    float mean = ss[0] * (1.f / TD);
    float rstd = rsqrtf(sv[0] * (1.f / TD) - mean * mean + LN_EPS);
#pragma unroll
    for (int p = 0; p < 3; p++) {
        int i = threadIdx.x + p * 256;
        g_h[(size_t)row * TD + i] =
            __float2bfloat16_rn((v[p] - mean) * rstd * gamma[i] + beta[i]);
    }
}

// ---------------- Weight transpose: wt[n][k] = W[k][n] (bf16) ----------------
__global__ __launch_bounds__(256) void wtrans_kernel(const float* __restrict__ Wq,
                                                     const float* __restrict__ Wk,
                                                     const float* __restrict__ Wv,
                                                     const float* __restrict__ Wo) {
    int z = blockIdx.z;
    const float* W = (z == 0) ? Wq : (z == 1) ? Wk : (z == 2) ? Wv : Wo;
    __shared__ float t[32][33];
    int n0 = blockIdx.x * 32, k0 = blockIdx.y * 32;
    int tx = threadIdx.x, ty = threadIdx.y;
#pragma unroll
    for (int i = 0; i < 4; i++)
        t[ty + 8 * i][tx] = W[(size_t)(k0 + ty + 8 * i) * TD + n0 + tx];
    __syncthreads();
#pragma unroll
    for (int i = 0; i < 4; i++)
        g_wt[z][(size_t)(n0 + ty + 8 * i) * TD + k0 + tx] =
            __float2bfloat16_rn(t[tx][ty + 8 * i]);
}

// ---------------- core 128x128 GEMM mainloop (cp.async double-buffered) -----
__device__ __forceinline__ void gemm128(const bf16* __restrict__ A, const bf16* __restrict__ Bt,
                                        char* smem, float c[4][4][4], int m0, int n0) {
    int tid = threadIdx.x, warp = tid >> 5, lane = tid & 31;
    int wm = (warp >> 2) * 64, wn = (warp & 3) * 32;
    uint32_t sb = smem_u32(smem);
    int arow = wm + (lane & 15);
    int acolx = (lane & 16) ? 16 : 0;
    int brow0 = wn + ((lane & 16) ? 8 : 0) + (lane & 7);
    int bcolx = (lane & 8) ? 16 : 0;

    int lr = tid >> 3, lch = tid & 7;
    uint32_t lsw[4];
#pragma unroll
    for (int p = 0; p < 4; p++) lsw[p] = row128(lr + p * 32, lch * 16);

#pragma unroll
    for (int p = 0; p < 4; p++) {
        int r = lr + p * 32;
        CP16(sb + lsw[p],         A  + (size_t)(m0 + r) * TD + lch * 8);
        CP16(sb + 16384 + lsw[p], Bt + (size_t)(n0 + r) * TD + lch * 8);
    }
    CP_COMMIT();

    for (int i = 0; i < 12; i++) {
        uint32_t stg = (uint32_t)(i & 1) * 32768;
        if (i < 11) {
            uint32_t nst = (uint32_t)((i + 1) & 1) * 32768;
#pragma unroll
            for (int p = 0; p < 4; p++) {
                int r = lr + p * 32;
                CP16(sb + nst + lsw[p],         A  + (size_t)(m0 + r) * TD + (i + 1) * 64 + lch * 8);
                CP16(sb + nst + 16384 + lsw[p], Bt + (size_t)(n0 + r) * TD + (i + 1) * 64 + lch * 8);
            }
            CP_COMMIT();
            CP_WAIT1();
        } else {
            CP_WAIT0();
        }
        __syncthreads();
#pragma unroll
        for (int ks = 0; ks < 4; ks++) {
            uint32_t af[4][4], bfr[4][2];
#pragma unroll
            for (int mf = 0; mf < 4; mf++)
                ldsm4(af[mf][0], af[mf][1], af[mf][2], af[mf][3],
                      sb + stg + row128(arow + mf * 16, ks * 32 + acolx));
#pragma unroll
            for (int j = 0; j < 4; j += 2)
                ldsm4(bfr[j][0], bfr[j][1], bfr[j + 1][0], bfr[j + 1][1],
                      sb + stg + 16384 + row128(brow0 + j * 8, ks * 32 + bcolx));
#pragma unroll
            for (int mf = 0; mf < 4; mf++)
#pragma unroll
                for (int nf = 0; nf < 4; nf++)
                    mma16816(c[mf][nf], af[mf], bfr[nf]);
        }
        __syncthreads();
    }
}

// ---------------- QKV GEMM (Q scaled by log2e; V written transposed) --------
#define GEMM_SMEM 65536
__global__ __launch_bounds__(256) void qkv_kernel() {
    extern __shared__ char smem[];
    int z = blockIdx.z;
    int m0 = blockIdx.x * 128, n0 = blockIdx.y * 128;
    float c[4][4][4] = {};
    gemm128(g_h, g_wt[z], smem, c, m0, n0);

    int tid = threadIdx.x, warp = tid >> 5, lane = tid & 31;
    int wm = (warp >> 2) * 64, wn = (warp & 3) * 32;

    if (z < 2) {
        bf16* G = (z == 0) ? g_q : g_k;
        float sc = (z == 0) ? LOG2E : 1.0f;   // fold exp->exp2 scaling into Q
#pragma unroll
        for (int mf = 0; mf < 4; mf++) {
            int row = m0 + wm + mf * 16 + (lane >> 2);
            int batch = row >> 11, seq = row & (NSEQ - 1);
#pragma unroll
            for (int nf = 0; nf < 4; nf++) {
                int col = n0 + wn + nf * 8 + 2 * (lane & 3);
                int head = col >> 6, d = col & 63;
                bf16* D = G + ((size_t)(batch * NHEADS + head) * NSEQ + seq) * HDIM + d;
                *(uint32_t*)D = pk2(c[mf][nf][0] * sc, c[mf][nf][1] * sc);
                *(uint32_t*)(D + 8 * HDIM) = pk2(c[mf][nf][2] * sc, c[mf][nf][3] * sc);
            }
        }
    } else {
        // V: transpose in smem, write g_vt[bh][d][seq] directly
        bf16* ts = (bf16*)smem;     // [128 cols n][136 pitch m]
        __syncthreads();            // gemm128 left smem free
#pragma unroll
        for (int mf = 0; mf < 4; mf++) {
            int lr0 = wm + mf * 16 + (lane >> 2);
#pragma unroll
            for (int nf = 0; nf < 4; nf++) {
                int lc = wn + nf * 8 + 2 * (lane & 3);
                uint32_t lo = pk2(c[mf][nf][0], c[mf][nf][2]);
                uint32_t hi = pk2(c[mf][nf][1], c[mf][nf][3]);
                ts[(size_t)lc * 136 + lr0]           = __ushort_as_bfloat16((unsigned short)(lo & 0xffff));
                ts[(size_t)lc * 136 + lr0 + 8]       = __ushort_as_bfloat16((unsigned short)(lo >> 16));
                ts[(size_t)(lc + 1) * 136 + lr0]     = __ushort_as_bfloat16((unsigned short)(hi & 0xffff));
                ts[(size_t)(lc + 1) * 136 + lr0 + 8] = __ushort_as_bfloat16((unsigned short)(hi >> 16));
            }
        }
        __syncthreads();
        int n = tid >> 1, mh = (tid & 1) * 64;
        int col = n0 + n, head = col >> 6, d = col & 63;
        int batch = blockIdx.x >> 4;
        int seq0 = (m0 & (NSEQ - 1)) + mh;
        bf16* D = g_vt + ((size_t)(batch * NHEADS + head) * HDIM + d) * NSEQ + seq0;
#pragma unroll
        for (int s = 0; s < 8; s++)
            *(uint4*)(D + s * 8) = *(uint4*)&ts[(size_t)n * 136 + mh + s * 8];
    }
}

// ---------------- Attention: 128 q/CTA, 4 warps x 32 q rows (2 m-frags) -----
// smem: Q 16K @0 | K 2x8K @16384 | V^T 2x8K @32768  (48KB static)
__global__ __launch_bounds__(128, 2) void attn_kernel() {
    __shared__ char smem[49152];
    int tid = threadIdx.x, warp = tid >> 5, lane = tid & 31;
    int q0 = blockIdx.x * 128, bh = blockIdx.y;

    const bf16* Qg = g_q + (size_t)bh * NSEQ * HDIM;
    const bf16* Kg = g_k + (size_t)bh * NSEQ * HDIM;
    const bf16* Vt = g_vt + (size_t)bh * HDIM * NSEQ;
    uint32_t sb = smem_u32(smem);

    // Q tile [128][64] (1024 uint4, 8 per thread)
#pragma unroll
    for (int p = 0; p < 8; p++) {
        int idx = tid + p * 128;
        int r = idx >> 3, ch = idx & 7;
        CP16(sb + row128(r, ch * 16), Qg + (size_t)(q0 + r) * HDIM + ch * 8);
    }
    CP_COMMIT();

    // K/V tile kt=0 into buf 0 (4 uint4 each per thread)
#pragma unroll
    for (int p = 0; p < 4; p++) {
        int idx = tid + p * 128;
        int r = idx >> 3, ch = idx & 7;
        uint32_t sw = row128(r, ch * 16);
        CP16(sb + 16384 + sw, Kg + (size_t)r * HDIM + ch * 8);
        CP16(sb + 32768 + sw, Vt + (size_t)r * NSEQ + ch * 8);
    }
    CP_COMMIT();

    CP_WAIT1();
    __syncthreads();

    // Q fragments: 32 rows per warp = 2 m-frags x 4 ksteps
    uint32_t qf[2][4][4];
    int arow = warp * 32 + (lane & 15);
    int acolx = (lane & 16) ? 16 : 0;
#pragma unroll
    for (int mf = 0; mf < 2; mf++)
#pragma unroll
        for (int ks = 0; ks < 4; ks++)
            ldsm4(qf[mf][ks][0], qf[mf][ks][1], qf[mf][ks][2], qf[mf][ks][3],
                  sb + row128(arow + mf * 16, ks * 32 + acolx));

    float of[2][8][4] = {};
    float lsum[2][2] = {};
    int brow0 = ((lane & 16) ? 8 : 0) + (lane & 7);
    int bcolx = (lane & 8) ? 16 : 0;

    for (int kt = 0; kt < NSEQ / 64; kt++) {
        uint32_t stg = (uint32_t)(kt & 1) * 8192;
        if (kt < NSEQ / 64 - 1) {
            uint32_t nst = (uint32_t)((kt + 1) & 1) * 8192;
#pragma unroll
            for (int p = 0; p < 4; p++) {
                int idx = tid + p * 128;
                int r = idx >> 3, ch = idx & 7;
                uint32_t sw = row128(r, ch * 16);
                CP16(sb + 16384 + nst + sw, Kg + (size_t)((kt + 1) * 64 + r) * HDIM + ch * 8);
                CP16(sb + 32768 + nst + sw, Vt + (size_t)r * NSEQ + (kt + 1) * 64 + ch * 8);
            }
            CP_COMMIT();
            CP_WAIT1();
        } else {
            CP_WAIT0();
        }
        __syncthreads();

        // S' = (log2e*Q) @ K^T in two 32-kv halves; P = exp2(S')
        uint32_t pf[2][4][4];
#pragma unroll
        for (int half = 0; half < 2; half++) {
            float sf[2][4][4] = {};
#pragma unroll
            for (int ks = 0; ks < 4; ks++) {
                uint32_t bfr[4][2];
#pragma unroll
                for (int j = 0; j < 4; j += 2)
                    ldsm4(bfr[j][0], bfr[j][1], bfr[j + 1][0], bfr[j + 1][1],
                          sb + 16384 + stg + row128(brow0 + half * 32 + j * 8, ks * 32 + bcolx));
#pragma unroll
                for (int mf = 0; mf < 2; mf++)
#pragma unroll
                    for (int nf = 0; nf < 4; nf++)
                        mma16816(sf[mf][nf], qf[mf][ks], bfr[nf]);
            }
#pragma unroll
            for (int mf = 0; mf < 2; mf++)
#pragma unroll
                for (int j = 0; j < 2; j++) {
                    float e00 = ex2(sf[mf][2 * j][0]),     e01 = ex2(sf[mf][2 * j][1]);
                    float e02 = ex2(sf[mf][2 * j][2]),     e03 = ex2(sf[mf][2 * j][3]);
                    float e10 = ex2(sf[mf][2 * j + 1][0]), e11 = ex2(sf[mf][2 * j + 1][1]);
                    float e12 = ex2(sf[mf][2 * j + 1][2]), e13 = ex2(sf[mf][2 * j + 1][3]);
                    int pj = half * 2 + j;
                    pf[mf][pj][0] = pk2(e00, e01);
                    pf[mf][pj][1] = pk2(e02, e03);
                    pf[mf][pj][2] = pk2(e10, e11);
                    pf[mf][pj][3] = pk2(e12, e13);
                    lsum[mf][0] += e00 + e01 + e10 + e11;
                    lsum[mf][1] += e02 + e03 + e12 + e13;
                }
        }

        // O += P @ V : B from V^T [d][kv]
#pragma unroll
        for (int ks = 0; ks < 4; ks++) {
            uint32_t bfr[8][2];
#pragma unroll
            for (int j = 0; j < 8; j += 2)
                ldsm4(bfr[j][0], bfr[j][1], bfr[j + 1][0], bfr[j + 1][1],
                      sb + 32768 + stg + row128(brow0 + j * 8, ks * 32 + bcolx));
#pragma unroll
            for (int mf = 0; mf < 2; mf++)
#pragma unroll
                for (int nf = 0; nf < 8; nf++)
                    mma16816(of[mf][nf], pf[mf][ks], bfr[nf]);
        }
        __syncthreads();
    }

    // reduce l across the quad, scale, store
    float scale[2][2];
#pragma unroll
    for (int mf = 0; mf < 2; mf++)
#pragma unroll
        for (int h = 0; h < 2; h++) {
            float l = lsum[mf][h];
            l += __shfl_xor_sync(~0u, l, 1);
            l += __shfl_xor_sync(~0u, l, 2);
            scale[mf][h] = ATT_SCALE / l;
        }
    int batch = bh / NHEADS, head = bh % NHEADS;
#pragma unroll
    for (int mf = 0; mf < 2; mf++) {
        int r0 = q0 + warp * 32 + mf * 16 + (lane >> 2);
#pragma unroll
        for (int nf = 0; nf < 8; nf++) {
            int d = nf * 8 + 2 * (lane & 3);
            bf16* D = g_vals + ((size_t)(batch * NSEQ + r0)) * TD + head * HDIM + d;
            *(uint32_t*)D = pk2(of[mf][nf][0] * scale[mf][0], of[mf][nf][1] * scale[mf][0]);
            *(uint32_t*)(D + (size_t)8 * TD) =
                pk2(of[mf][nf][2] * scale[mf][1], of[mf][nf][3] * scale[mf][1]);
        }
    }
}

// ---------------- Output projection: out = vals @ Wo + bo + x ----------------
__global__ __launch_bounds__(256) void out_kernel(const float* __restrict__ bo,
                                                  const float* __restrict__ x,
                                                  float* __restrict__ out) {
    extern __shared__ char smem[];
    int m0 = blockIdx.x * 128, n0 = blockIdx.y * 128;
    float c[4][4][4] = {};
    gemm128(g_vals, g_wt[3], smem, c, m0, n0);

    int tid = threadIdx.x, warp = tid >> 5, lane = tid & 31;
    int wm = (warp >> 2) * 64, wn = (warp & 3) * 32;
#pragma unroll
    for (int mf = 0; mf < 4; mf++) {
        int row = m0 + wm + mf * 16 + (lane >> 2);
#pragma unroll
        for (int nf = 0; nf < 4; nf++) {
            int col = n0 + wn + nf * 8 + 2 * (lane & 3);
            float2 bv = *(const float2*)(bo + col);
            size_t off0 = (size_t)row * TD + col;
            size_t off1 = (size_t)(row + 8) * TD + col;
            float2 x0 = *(const float2*)(x + off0);
            float2 x1 = *(const float2*)(x + off1);
            *(float2*)(out + off0) = make_float2(c[mf][nf][0] + bv.x + x0.x,
                                                 c[mf][nf][1] + bv.y + x0.y);
            *(float2*)(out + off1) = make_float2(c[mf][nf][2] + bv.x + x1.x,
                                                 c[mf][nf][3] + bv.y + x1.y);
        }
    }
}

// ---------------------------------------------------------------------------
extern "C" void kernel_launch(void* const* d_in, const int* in_sizes, int n_in,
                              void* d_out, int out_size) {
    (void)in_sizes; (void)n_in; (void)out_size;
    const float* x     = (const float*)d_in[0];
    const float* Wq    = (const float*)d_in[1];
    const float* Wk    = (const float*)d_in[2];
    const float* Wv    = (const float*)d_in[3];
    const float* Wo    = (const float*)d_in[4];
    const float* bo    = (const float*)d_in[5];
    const float* gamma = (const float*)d_in[6];
    const float* beta  = (const float*)d_in[7];
    float* out = (float*)d_out;

    cudaFuncSetAttribute(qkv_kernel, cudaFuncAttributeMaxDynamicSharedMemorySize, GEMM_SMEM);
    cudaFuncSetAttribute(out_kernel, cudaFuncAttributeMaxDynamicSharedMemorySize, GEMM_SMEM);

    ln_kernel<<<NROWS, 256>>>(x, gamma, beta);
    wtrans_kernel<<<dim3(TD / 32, TD / 32, 4), dim3(32, 8)>>>(Wq, Wk, Wv, Wo);
    qkv_kernel<<<dim3(NROWS / 128, TD / 128, 3), 256, GEMM_SMEM>>>();
    attn_kernel<<<dim3(NSEQ / 128, NBH), 128>>>();
    out_kernel<<<dim3(NROWS / 128, TD / 128), 256, GEMM_SMEM>>>(bo, x, out);
}